// round 1
// baseline (speedup 1.0000x reference)
#include <cuda_runtime.h>
#include <cstdint>

typedef unsigned long long ull;

// ---------- packed f32x2 helpers (Blackwell sm_100+) ----------
#define FMA_F32X2(d, a, b, c) \
    asm("fma.rn.f32x2 %0, %1, %2, %3;" : "=l"(d) : "l"(a), "l"(b), "l"(c))

__device__ __forceinline__ ull pack_dup(float x) {
    ull r; unsigned u = __float_as_uint(x);
    asm("mov.b64 %0, {%1, %1};" : "=l"(r) : "r"(u));
    return r;
}
__device__ __forceinline__ ull pack2(float lo, float hi) {
    ull r;
    asm("mov.b64 %0, {%1, %2};" : "=l"(r) : "r"(__float_as_uint(lo)), "r"(__float_as_uint(hi)));
    return r;
}
__device__ __forceinline__ float2 unpack2(ull v) {
    unsigned lo, hi;
    asm("mov.b64 {%0, %1}, %2;" : "=r"(lo), "=r"(hi) : "l"(v));
    return make_float2(__uint_as_float(lo), __uint_as_float(hi));
}

// ---------- scratch (device globals; no allocation allowed) ----------
__device__ float g_wT1[1024 * 9 * 256];      // w_reduce transposed [ci][k][co]
__device__ float g_wT2[512 * 9 * 256];       // w2 transposed
__device__ float g_buf1[4 * 512 * 64 * 64];  // concat(relu(conv1(cur)), relu(conv1(key)))
__device__ float g_buf2[4 * 256 * 64 * 64];  // relu(conv2)
__device__ float g_kern[4 * 81 * 64 * 64];   // softmax kernels

// ---------- weight transpose: w (COUT=256, CIN, 3,3) -> wT[(ci*9+k)*256 + co] ----------
__global__ void transpose_w_kernel(const float* __restrict__ w, float* __restrict__ wT,
                                   int CIN, int total) {
    int i = blockIdx.x * 256 + threadIdx.x;
    if (i >= total) return;
    int co = i & 255;
    int t = i >> 8;
    int k = t % 9;
    int ci = t / 9;
    wT[i] = w[((size_t)co * CIN + ci) * 9 + k];
}

// ---------- 3x3 conv + bias + relu, direct conv, fp32x2 ----------
// Block tile: 32(W) x 8(H) pixels x 32 out-channels. 256 threads:
//   tx = tid&3 (8-px column segment), ty = (tid>>2)&7 (row), tc = tid>>5 (4-ch group)
// Each thread: 8 px x 4 ch = 32 outputs = 16 f32x2 accumulators.
constexpr int KC = 8;          // input-channel chunk
constexpr int XS_ROW = 35;     // odd stride -> conflict-free LDS for (ty,tx) lane map
constexpr int XS_PLANE = 10 * XS_ROW;  // 350

template <int CIN>
__global__ void __launch_bounds__(256) conv3x3_relu_kernel(
    const float* __restrict__ x, const float* __restrict__ wT,
    const float* __restrict__ bias, float* __restrict__ out,
    int outChan, int ocOff)
{
    __shared__ __align__(16) float x_s[KC * XS_PLANE];   // 2800 floats
    __shared__ __align__(16) float w_s[32 * KC * 9];     // 2304 floats

    const int tid = threadIdx.x;
    const int tx = tid & 3;
    const int ty = (tid >> 2) & 7;
    const int tc = tid >> 5;
    const int w0 = blockIdx.x * 32;
    const int h0 = blockIdx.y * 8;
    const int b  = blockIdx.z >> 3;
    const int oc0 = (blockIdx.z & 7) * 32;
    const int ch0 = oc0 + tc * 4;

    ull acc[2][8];
    {
        ull b0 = pack2(bias[ch0],     bias[ch0 + 1]);
        ull b1 = pack2(bias[ch0 + 2], bias[ch0 + 3]);
        #pragma unroll
        for (int p = 0; p < 8; p++) { acc[0][p] = b0; acc[1][p] = b1; }
    }

    const float* xb = x + (size_t)b * CIN * 4096;

    for (int c0 = 0; c0 < CIN; c0 += KC) {
        __syncthreads();
        // stage input tile (KC x 10 x 34) with zero padding
        for (int j = tid; j < KC * 10 * 34; j += 256) {
            int cc = j / 340;
            int rem = j - cc * 340;
            int r = rem / 34;
            int c = rem - r * 34;
            int gr = h0 + r - 1, gc = w0 + c - 1;
            float v = 0.f;
            if ((unsigned)gr < 64u && (unsigned)gc < 64u)
                v = xb[(size_t)(c0 + cc) * 4096 + gr * 64 + gc];
            x_s[cc * XS_PLANE + r * XS_ROW + c] = v;
        }
        // stage weights: w_s[(cc*9+k)*32 + ch], coalesced from transposed layout
        #pragma unroll
        for (int it = 0; it < 9; it++) {
            int j = tid + it * 256;
            int ch = j & 31;
            int t = j >> 5;
            int k = t % 9;
            int cc = t / 9;
            w_s[j] = wT[(size_t)((c0 + cc) * 9 + k) * 256 + oc0 + ch];
        }
        __syncthreads();

        #pragma unroll 1
        for (int cc = 0; cc < KC; cc++) {
            #pragma unroll
            for (int ki = 0; ki < 3; ki++) {
                const float* xr = &x_s[cc * XS_PLANE + (ty + ki) * XS_ROW + tx * 8];
                ull xp[10];
                #pragma unroll
                for (int t = 0; t < 10; t++) xp[t] = pack_dup(xr[t]);
                #pragma unroll
                for (int kj = 0; kj < 3; kj++) {
                    const float* wr = &w_s[(cc * 9 + ki * 3 + kj) * 32 + tc * 4];
                    ull wv0 = *reinterpret_cast<const ull*>(wr);
                    ull wv1 = *reinterpret_cast<const ull*>(wr + 2);
                    #pragma unroll
                    for (int p = 0; p < 8; p++) {
                        FMA_F32X2(acc[0][p], xp[kj + p], wv0, acc[0][p]);
                        FMA_F32X2(acc[1][p], xp[kj + p], wv1, acc[1][p]);
                    }
                }
            }
        }
    }

    // relu + store (vectorized): channels ch0..ch0+3, 8 px each
    #pragma unroll
    for (int c2 = 0; c2 < 2; c2++) {
        float lo[8], hi[8];
        #pragma unroll
        for (int p = 0; p < 8; p++) {
            float2 v = unpack2(acc[c2][p]);
            lo[p] = fmaxf(v.x, 0.f);
            hi[p] = fmaxf(v.y, 0.f);
        }
        size_t base = ((size_t)(b * outChan + ocOff + ch0 + c2 * 2) * 4096)
                    + (size_t)(h0 + ty) * 64 + w0 + tx * 8;
        *reinterpret_cast<float4*>(&out[base])          = make_float4(lo[0], lo[1], lo[2], lo[3]);
        *reinterpret_cast<float4*>(&out[base + 4])      = make_float4(lo[4], lo[5], lo[6], lo[7]);
        *reinterpret_cast<float4*>(&out[base + 4096])   = make_float4(hi[0], hi[1], hi[2], hi[3]);
        *reinterpret_cast<float4*>(&out[base + 4100])   = make_float4(hi[4], hi[5], hi[6], hi[7]);
    }
}

// ---------- 1x1 conv (256->81) + bias + relu + softmax over 81 ----------
// One block per (b, h) row: 64 px. 256 threads = 64 px x 4 co-groups (co = grp + 4k).
__global__ void __launch_bounds__(256) conv1x1_softmax_kernel(
    const float* __restrict__ x2, const float* __restrict__ w3,
    const float* __restrict__ b3, float* __restrict__ kout)
{
    __shared__ float s_w[81 * 64];      // weight chunk: 81 co x 64 ci
    __shared__ float s_logit[81 * 64];  // relu'd logits per px
    __shared__ float s_m[64];
    __shared__ float s_r[64];

    const int tid = threadIdx.x;
    const int px = tid & 63;
    const int grp = tid >> 6;
    const int h = blockIdx.x;
    const int b = blockIdx.y;

    float acc[21];
    #pragma unroll
    for (int k = 0; k < 21; k++) {
        int co = grp + 4 * k;
        acc[k] = (co < 81) ? b3[co] : 0.f;
    }

    const float* xb = x2 + ((size_t)b * 256) * 4096 + h * 64 + px;

    for (int ci0 = 0; ci0 < 256; ci0 += 64) {
        __syncthreads();
        for (int j = tid; j < 81 * 64; j += 256) {
            int co = j >> 6;
            int i = j & 63;
            s_w[j] = w3[co * 256 + ci0 + i];
        }
        __syncthreads();
        for (int i = 0; i < 64; i++) {
            float xv = __ldg(xb + (size_t)(ci0 + i) * 4096);
            #pragma unroll
            for (int k = 0; k < 21; k++) {
                int co = grp + 4 * k;
                if (co < 81) acc[k] += xv * s_w[co * 64 + i];
            }
        }
    }

    #pragma unroll
    for (int k = 0; k < 21; k++) {
        int co = grp + 4 * k;
        if (co < 81) s_logit[co * 64 + px] = fmaxf(acc[k], 0.f);
    }
    __syncthreads();

    if (tid < 64) {
        float m = -1e30f;
        for (int co = 0; co < 81; co++) m = fmaxf(m, s_logit[co * 64 + tid]);
        float s = 0.f;
        for (int co = 0; co < 81; co++) s += __expf(s_logit[co * 64 + tid] - m);
        s_m[tid] = m;
        s_r[tid] = 1.f / s;
    }
    __syncthreads();

    float m = s_m[px], r = s_r[px];
    #pragma unroll
    for (int k = 0; k < 21; k++) {
        int co = grp + 4 * k;
        if (co < 81)
            kout[((size_t)(b * 81 + co) * 4096) + h * 64 + px] =
                __expf(s_logit[co * 64 + px] - m) * r;
    }
}

// ---------- spatially-variant 9x9 conv ----------
// Block: 8x8 spatial tile x 16 channels. 256 threads = 64 px x 4 channel-quads.
// smem: 81x64 kernel tile (reused across all channels) + 16x16x16 feature halo tile.
__global__ void __launch_bounds__(256) svc_kernel(
    const float* __restrict__ feats, const float* __restrict__ kern,
    float* __restrict__ out)
{
    __shared__ float k_s[81 * 64];          // 20736 B
    __shared__ float f_s[16 * 16 * 24];     // row stride 24 -> conflict-free

    const int tid = threadIdx.x;
    const int px_x = tid & 7;
    const int py = (tid >> 3) & 7;
    const int cq = tid >> 6;
    const int px = py * 8 + px_x;
    const int w0 = blockIdx.x * 8;
    const int h0 = blockIdx.y * 8;
    const int b = blockIdx.z >> 6;
    const int cbase = (blockIdx.z & 63) * 16;

    for (int j = tid; j < 81 * 64; j += 256) {
        int idx = j >> 6;
        int p = j & 63;
        k_s[j] = kern[((size_t)(b * 81 + idx) * 64 + h0 + (p >> 3)) * 64 + w0 + (p & 7)];
    }
    for (int j = tid; j < 16 * 16 * 16; j += 256) {
        int c = j >> 8;
        int r = (j >> 4) & 15;
        int col = j & 15;
        int gr = h0 + r - 4, gc = w0 + col - 4;
        float v = 0.f;
        if ((unsigned)gr < 64u && (unsigned)gc < 64u)
            v = feats[((size_t)(b * 1024 + cbase + c) * 4096) + gr * 64 + gc];
        f_s[c * 384 + r * 24 + col] = v;
    }
    __syncthreads();

    float acc[4] = {0.f, 0.f, 0.f, 0.f};
    #pragma unroll 1
    for (int i = 0; i < 9; i++) {
        const int fb = (py + i) * 24 + px_x + (cq * 4) * 384;
        #pragma unroll
        for (int j = 0; j < 9; j++) {
            float kv = k_s[(i * 9 + j) * 64 + px];
            #pragma unroll
            for (int c = 0; c < 4; c++)
                acc[c] += f_s[fb + j + c * 384] * kv;
        }
    }

    size_t ob = ((size_t)(b * 1024 + cbase + cq * 4) * 4096)
              + (size_t)(h0 + py) * 64 + w0 + px_x;
    #pragma unroll
    for (int c = 0; c < 4; c++)
        out[ob + (size_t)c * 4096] = acc[c];
}

// ---------- launch ----------
extern "C" void kernel_launch(void* const* d_in, const int* in_sizes, int n_in,
                              void* d_out, int out_size)
{
    (void)in_sizes; (void)n_in; (void)out_size;
    const float* cur  = (const float*)d_in[0];
    const float* keyl = (const float*)d_in[1];
    const float* high = (const float*)d_in[2];
    const float* w1   = (const float*)d_in[3];
    const float* b1   = (const float*)d_in[4];
    const float* w2   = (const float*)d_in[5];
    const float* b2   = (const float*)d_in[6];
    const float* w3   = (const float*)d_in[7];
    const float* b3   = (const float*)d_in[8];
    float* out = (float*)d_out;

    float *wT1, *wT2, *buf1, *buf2, *kern;
    cudaGetSymbolAddress((void**)&wT1,  g_wT1);
    cudaGetSymbolAddress((void**)&wT2,  g_wT2);
    cudaGetSymbolAddress((void**)&buf1, g_buf1);
    cudaGetSymbolAddress((void**)&buf2, g_buf2);
    cudaGetSymbolAddress((void**)&kern, g_kern);

    transpose_w_kernel<<<(1024 * 9 * 256 + 255) / 256, 256>>>(w1, wT1, 1024, 1024 * 9 * 256);
    transpose_w_kernel<<<(512 * 9 * 256 + 255) / 256, 256>>>(w2, wT2, 512, 512 * 9 * 256);

    dim3 cgrid(2, 8, 32);
    conv3x3_relu_kernel<1024><<<cgrid, 256>>>(cur,  wT1, b1, buf1, 512, 0);
    conv3x3_relu_kernel<1024><<<cgrid, 256>>>(keyl, wT1, b1, buf1, 512, 256);
    conv3x3_relu_kernel<512><<<cgrid, 256>>>(buf1, wT2, b2, buf2, 256, 0);

    conv1x1_softmax_kernel<<<dim3(64, 4), 256>>>(buf2, w3, b3, kern);

    svc_kernel<<<dim3(8, 8, 256), 256>>>(high, kern, out);
}

// round 2
// speedup vs baseline: 1.0046x; 1.0046x over previous
#include <cuda_runtime.h>
#include <cstdint>

typedef unsigned long long ull;

// ---------- packed f32x2 helpers (Blackwell sm_100+) ----------
#define FMA_F32X2(d, a, b, c) \
    asm("fma.rn.f32x2 %0, %1, %2, %3;" : "=l"(d) : "l"(a), "l"(b), "l"(c))

__device__ __forceinline__ ull pack_dup(float x) {
    ull r; unsigned u = __float_as_uint(x);
    asm("mov.b64 %0, {%1, %1};" : "=l"(r) : "r"(u));
    return r;
}
__device__ __forceinline__ ull pack2(float lo, float hi) {
    ull r;
    asm("mov.b64 %0, {%1, %2};" : "=l"(r) : "r"(__float_as_uint(lo)), "r"(__float_as_uint(hi)));
    return r;
}
__device__ __forceinline__ float2 unpack2(ull v) {
    unsigned lo, hi;
    asm("mov.b64 {%0, %1}, %2;" : "=r"(lo), "=r"(hi) : "l"(v));
    return make_float2(__uint_as_float(lo), __uint_as_float(hi));
}

// ---------- scratch (device globals; no allocation allowed) ----------
__device__ float g_wT1[1024 * 9 * 256];      // w_reduce transposed [ci][k][co]
__device__ float g_wT2[512 * 9 * 256];       // w2 transposed
__device__ float g_buf1[4 * 512 * 64 * 64];  // concat(relu(conv1(cur)), relu(conv1(key)))
__device__ float g_buf2[4 * 256 * 64 * 64];  // relu(conv2)
__device__ float g_kern[4 * 81 * 64 * 64];   // softmax kernels

// ---------- weight transpose: w (COUT=256, CIN, 3,3) -> wT[(ci*9+k)*256 + co] ----------
__global__ void transpose_w_kernel(const float* __restrict__ w, float* __restrict__ wT,
                                   int CIN, int total) {
    int i = blockIdx.x * 256 + threadIdx.x;
    if (i >= total) return;
    int co = i & 255;
    int t = i >> 8;
    int k = t % 9;
    int ci = t / 9;
    wT[i] = w[((size_t)co * CIN + ci) * 9 + k];
}

// ---------- 3x3 conv + bias + relu, direct conv, fp32x2 ----------
// Block tile: 32(W) x 8(H) pixels x 32 out-channels. 256 threads:
//   tx = tid&3 (8-px column segment), ty = (tid>>2)&7 (row), tc = tid>>5 (4-ch group)
// Each thread: 8 px x 4 ch = 32 outputs = 16 f32x2 accumulators.
constexpr int KC = 8;          // input-channel chunk
constexpr int XS_ROW = 35;     // odd stride -> conflict-free LDS for (ty,tx) lane map
constexpr int XS_PLANE = 10 * XS_ROW;  // 350

template <int CIN>
__global__ void __launch_bounds__(256) conv3x3_relu_kernel(
    const float* __restrict__ x, const float* __restrict__ wT,
    const float* __restrict__ bias, float* __restrict__ out,
    int outChan, int ocOff)
{
    __shared__ __align__(16) float x_s[KC * XS_PLANE];   // 2800 floats
    __shared__ __align__(16) float w_s[32 * KC * 9];     // 2304 floats

    const int tid = threadIdx.x;
    const int tx = tid & 3;
    const int ty = (tid >> 2) & 7;
    const int tc = tid >> 5;
    const int w0 = blockIdx.x * 32;
    const int h0 = blockIdx.y * 8;
    const int b  = blockIdx.z >> 3;
    const int oc0 = (blockIdx.z & 7) * 32;
    const int ch0 = oc0 + tc * 4;

    ull acc[2][8];
    {
        ull b0 = pack2(bias[ch0],     bias[ch0 + 1]);
        ull b1 = pack2(bias[ch0 + 2], bias[ch0 + 3]);
        #pragma unroll
        for (int p = 0; p < 8; p++) { acc[0][p] = b0; acc[1][p] = b1; }
    }

    const float* xb = x + (size_t)b * CIN * 4096;

    for (int c0 = 0; c0 < CIN; c0 += KC) {
        __syncthreads();
        // stage input tile (KC x 10 x 34) with zero padding
        for (int j = tid; j < KC * 10 * 34; j += 256) {
            int cc = j / 340;
            int rem = j - cc * 340;
            int r = rem / 34;
            int c = rem - r * 34;
            int gr = h0 + r - 1, gc = w0 + c - 1;
            float v = 0.f;
            if ((unsigned)gr < 64u && (unsigned)gc < 64u)
                v = xb[(size_t)(c0 + cc) * 4096 + gr * 64 + gc];
            x_s[cc * XS_PLANE + r * XS_ROW + c] = v;
        }
        // stage weights: w_s[(cc*9+k)*32 + ch], coalesced from transposed layout
        #pragma unroll
        for (int it = 0; it < 9; it++) {
            int j = tid + it * 256;
            int ch = j & 31;
            int t = j >> 5;
            int k = t % 9;
            int cc = t / 9;
            w_s[j] = wT[(size_t)((c0 + cc) * 9 + k) * 256 + oc0 + ch];
        }
        __syncthreads();

        #pragma unroll 1
        for (int cc = 0; cc < KC; cc++) {
            #pragma unroll
            for (int ki = 0; ki < 3; ki++) {
                const float* xr = &x_s[cc * XS_PLANE + (ty + ki) * XS_ROW + tx * 8];
                ull xp[10];
                #pragma unroll
                for (int t = 0; t < 10; t++) xp[t] = pack_dup(xr[t]);
                #pragma unroll
                for (int kj = 0; kj < 3; kj++) {
                    const float* wr = &w_s[(cc * 9 + ki * 3 + kj) * 32 + tc * 4];
                    ull wv0 = *reinterpret_cast<const ull*>(wr);
                    ull wv1 = *reinterpret_cast<const ull*>(wr + 2);
                    #pragma unroll
                    for (int p = 0; p < 8; p++) {
                        FMA_F32X2(acc[0][p], xp[kj + p], wv0, acc[0][p]);
                        FMA_F32X2(acc[1][p], xp[kj + p], wv1, acc[1][p]);
                    }
                }
            }
        }
    }

    // relu + store (vectorized): channels ch0..ch0+3, 8 px each
    #pragma unroll
    for (int c2 = 0; c2 < 2; c2++) {
        float lo[8], hi[8];
        #pragma unroll
        for (int p = 0; p < 8; p++) {
            float2 v = unpack2(acc[c2][p]);
            lo[p] = fmaxf(v.x, 0.f);
            hi[p] = fmaxf(v.y, 0.f);
        }
        size_t base = ((size_t)(b * outChan + ocOff + ch0 + c2 * 2) * 4096)
                    + (size_t)(h0 + ty) * 64 + w0 + tx * 8;
        *reinterpret_cast<float4*>(&out[base])          = make_float4(lo[0], lo[1], lo[2], lo[3]);
        *reinterpret_cast<float4*>(&out[base + 4])      = make_float4(lo[4], lo[5], lo[6], lo[7]);
        *reinterpret_cast<float4*>(&out[base + 4096])   = make_float4(hi[0], hi[1], hi[2], hi[3]);
        *reinterpret_cast<float4*>(&out[base + 4100])   = make_float4(hi[4], hi[5], hi[6], hi[7]);
    }
}

// ---------- 1x1 conv (256->81) + bias + relu + softmax over 81 ----------
// One block per (b, h) row: 64 px. 256 threads = 64 px x 4 co-groups (co = grp + 4k).
__global__ void __launch_bounds__(256) conv1x1_softmax_kernel(
    const float* __restrict__ x2, const float* __restrict__ w3,
    const float* __restrict__ b3, float* __restrict__ kout)
{
    __shared__ float s_w[81 * 64];      // weight chunk: 81 co x 64 ci
    __shared__ float s_logit[81 * 64];  // relu'd logits per px
    __shared__ float s_m[64];
    __shared__ float s_r[64];

    const int tid = threadIdx.x;
    const int px = tid & 63;
    const int grp = tid >> 6;
    const int h = blockIdx.x;
    const int b = blockIdx.y;

    float acc[21];
    #pragma unroll
    for (int k = 0; k < 21; k++) {
        int co = grp + 4 * k;
        acc[k] = (co < 81) ? b3[co] : 0.f;
    }

    const float* xb = x2 + ((size_t)b * 256) * 4096 + h * 64 + px;

    for (int ci0 = 0; ci0 < 256; ci0 += 64) {
        __syncthreads();
        for (int j = tid; j < 81 * 64; j += 256) {
            int co = j >> 6;
            int i = j & 63;
            s_w[j] = w3[co * 256 + ci0 + i];
        }
        __syncthreads();
        for (int i = 0; i < 64; i++) {
            float xv = __ldg(xb + (size_t)(ci0 + i) * 4096);
            #pragma unroll
            for (int k = 0; k < 21; k++) {
                int co = grp + 4 * k;
                if (co < 81) acc[k] += xv * s_w[co * 64 + i];
            }
        }
    }

    #pragma unroll
    for (int k = 0; k < 21; k++) {
        int co = grp + 4 * k;
        if (co < 81) s_logit[co * 64 + px] = fmaxf(acc[k], 0.f);
    }
    __syncthreads();

    if (tid < 64) {
        float m = -1e30f;
        for (int co = 0; co < 81; co++) m = fmaxf(m, s_logit[co * 64 + tid]);
        float s = 0.f;
        for (int co = 0; co < 81; co++) s += __expf(s_logit[co * 64 + tid] - m);
        s_m[tid] = m;
        s_r[tid] = 1.f / s;
    }
    __syncthreads();

    float m = s_m[px], r = s_r[px];
    #pragma unroll
    for (int k = 0; k < 21; k++) {
        int co = grp + 4 * k;
        if (co < 81)
            kout[((size_t)(b * 81 + co) * 4096) + h * 64 + px] =
                __expf(s_logit[co * 64 + px] - m) * r;
    }
}

// ---------- spatially-variant 9x9 conv ----------
// Block: 8x8 spatial tile x 16 channels. 256 threads = 64 px x 4 channel-quads.
// smem: 81x64 kernel tile (reused across all channels) + 16x16x16 feature halo tile.
__global__ void __launch_bounds__(256) svc_kernel(
    const float* __restrict__ feats, const float* __restrict__ kern,
    float* __restrict__ out)
{
    __shared__ float k_s[81 * 64];          // 20736 B
    __shared__ float f_s[16 * 16 * 24];     // row stride 24 -> conflict-free

    const int tid = threadIdx.x;
    const int px_x = tid & 7;
    const int py = (tid >> 3) & 7;
    const int cq = tid >> 6;
    const int px = py * 8 + px_x;
    const int w0 = blockIdx.x * 8;
    const int h0 = blockIdx.y * 8;
    const int b = blockIdx.z >> 6;
    const int cbase = (blockIdx.z & 63) * 16;

    for (int j = tid; j < 81 * 64; j += 256) {
        int idx = j >> 6;
        int p = j & 63;
        k_s[j] = kern[((size_t)(b * 81 + idx) * 64 + h0 + (p >> 3)) * 64 + w0 + (p & 7)];
    }
    for (int j = tid; j < 16 * 16 * 16; j += 256) {
        int c = j >> 8;
        int r = (j >> 4) & 15;
        int col = j & 15;
        int gr = h0 + r - 4, gc = w0 + col - 4;
        float v = 0.f;
        if ((unsigned)gr < 64u && (unsigned)gc < 64u)
            v = feats[((size_t)(b * 1024 + cbase + c) * 4096) + gr * 64 + gc];
        f_s[c * 384 + r * 24 + col] = v;
    }
    __syncthreads();

    float acc[4] = {0.f, 0.f, 0.f, 0.f};
    #pragma unroll 1
    for (int i = 0; i < 9; i++) {
        const int fb = (py + i) * 24 + px_x + (cq * 4) * 384;
        #pragma unroll
        for (int j = 0; j < 9; j++) {
            float kv = k_s[(i * 9 + j) * 64 + px];
            #pragma unroll
            for (int c = 0; c < 4; c++)
                acc[c] += f_s[fb + j + c * 384] * kv;
        }
    }

    size_t ob = ((size_t)(b * 1024 + cbase + cq * 4) * 4096)
              + (size_t)(h0 + py) * 64 + w0 + px_x;
    #pragma unroll
    for (int c = 0; c < 4; c++)
        out[ob + (size_t)c * 4096] = acc[c];
}

// ---------- launch ----------
extern "C" void kernel_launch(void* const* d_in, const int* in_sizes, int n_in,
                              void* d_out, int out_size)
{
    (void)in_sizes; (void)n_in; (void)out_size;
    const float* cur  = (const float*)d_in[0];
    const float* keyl = (const float*)d_in[1];
    const float* high = (const float*)d_in[2];
    const float* w1   = (const float*)d_in[3];
    const float* b1   = (const float*)d_in[4];
    const float* w2   = (const float*)d_in[5];
    const float* b2   = (const float*)d_in[6];
    const float* w3   = (const float*)d_in[7];
    const float* b3   = (const float*)d_in[8];
    float* out = (float*)d_out;

    float *wT1, *wT2, *buf1, *buf2, *kern;
    cudaGetSymbolAddress((void**)&wT1,  g_wT1);
    cudaGetSymbolAddress((void**)&wT2,  g_wT2);
    cudaGetSymbolAddress((void**)&buf1, g_buf1);
    cudaGetSymbolAddress((void**)&buf2, g_buf2);
    cudaGetSymbolAddress((void**)&kern, g_kern);

    transpose_w_kernel<<<(1024 * 9 * 256 + 255) / 256, 256>>>(w1, wT1, 1024, 1024 * 9 * 256);
    transpose_w_kernel<<<(512 * 9 * 256 + 255) / 256, 256>>>(w2, wT2, 512, 512 * 9 * 256);

    dim3 cgrid(2, 8, 32);
    conv3x3_relu_kernel<1024><<<cgrid, 256>>>(cur,  wT1, b1, buf1, 512, 0);
    conv3x3_relu_kernel<1024><<<cgrid, 256>>>(keyl, wT1, b1, buf1, 512, 256);
    conv3x3_relu_kernel<512><<<cgrid, 256>>>(buf1, wT2, b2, buf2, 256, 0);

    conv1x1_softmax_kernel<<<dim3(64, 4), 256>>>(buf2, w3, b3, kern);

    svc_kernel<<<dim3(8, 8, 256), 256>>>(high, kern, out);
}

// round 4
// speedup vs baseline: 1.8283x; 1.8199x over previous
#include <cuda_runtime.h>
#include <cuda_bf16.h>
#include <cstdint>

typedef unsigned u32; typedef unsigned long long u64;
typedef __nv_bfloat16 bf16;

// ===================== PTX helpers (portable: sm_80-class only) =====================
__device__ __forceinline__ u32 smem_u32(const void* p){
    u32 a; asm("{ .reg .u64 t; cvta.to.shared.u64 t, %1; cvt.u32.u64 %0, t; }":"=r"(a):"l"(p)); return a;
}
#define CP_ASYNC_CA(dst, src, sz) \
    asm volatile("cp.async.ca.shared.global [%0], [%1], 16, %2;" :: "r"(dst), "l"(src), "r"(sz))
#define CP_ASYNC_CG(dst, src) \
    asm volatile("cp.async.cg.shared.global [%0], [%1], 16;" :: "r"(dst), "l"(src))
#define CP_COMMIT() asm volatile("cp.async.commit_group;" ::: "memory")
#define CP_WAIT(N)  asm volatile("cp.async.wait_group %0;" :: "n"(N) : "memory")

__device__ __forceinline__ void ldm_x4(u32* r, u32 addr){
    asm volatile("ldmatrix.sync.aligned.m8n8.x4.shared.b16 {%0,%1,%2,%3}, [%4];"
        : "=r"(r[0]),"=r"(r[1]),"=r"(r[2]),"=r"(r[3]) : "r"(addr));
}
__device__ __forceinline__ void mma_bf16(float* c, const u32* a, const u32* b){
    asm volatile("mma.sync.aligned.m16n8k16.row.col.f32.bf16.bf16.f32 "
        "{%0,%1,%2,%3}, {%4,%5,%6,%7}, {%8,%9}, {%0,%1,%2,%3};"
        : "+f"(c[0]),"+f"(c[1]),"+f"(c[2]),"+f"(c[3])
        : "r"(a[0]),"r"(a[1]),"r"(a[2]),"r"(a[3]), "r"(b[0]),"r"(b[1]));
}
__device__ __forceinline__ void bf16_split(float v, bf16& h, bf16& l){
    h = __float2bfloat16(v);
    l = __float2bfloat16(v - __bfloat162float(h));
}
__device__ __forceinline__ u32 pack_bf16(bf16 a, bf16 b){
    return (u32)__bfloat16_as_ushort(a) | ((u32)__bfloat16_as_ushort(b) << 16);
}

// ===================== device scratch =====================
__device__ bf16 g_x0h[4ULL*4096*1024];
__device__ bf16 g_x0l[4ULL*4096*1024];
__device__ bf16 g_x1h[4ULL*4096*1024];
__device__ bf16 g_x1l[4ULL*4096*1024];
__device__ bf16 g_w1h[9*32*256*32];
__device__ bf16 g_w1l[9*32*256*32];
__device__ bf16 g_w2h[9*16*256*32];
__device__ bf16 g_w2l[9*16*256*32];
__device__ bf16 g_b1h[4ULL*4096*512];   // NHWC bf16-hi of concat(cur,key) conv1 output
__device__ bf16 g_b1l[4ULL*4096*512];
__device__ float g_buf2[4ULL*256*4096]; // NCHW conv2 output
__device__ float g_kern[4ULL*81*4096];  // NCHW softmax kernels

// ===================== NCHW fp32 -> NHWC bf16 hi/lo (C=1024) =====================
__global__ void __launch_bounds__(256) transpose_split(
    const float* __restrict__ x, bf16* __restrict__ xh, bf16* __restrict__ xl)
{
    __shared__ float s[64*65];
    const int tid = threadIdx.x, px0 = blockIdx.x*64, ci0 = blockIdx.y*64, b = blockIdx.z;
    for (int j = tid; j < 4096; j += 256){
        int ci = j>>6, p = j&63;
        s[ci*65+p] = x[((size_t)(b*1024 + ci0+ci))*4096 + px0 + p];
    }
    __syncthreads();
    for (int j = tid; j < 2048; j += 256){
        int p = j>>5, ci2 = (j&31)*2;
        float v0 = s[ci2*65+p], v1 = s[(ci2+1)*65+p];
        bf16 h0,l0,h1,l1; bf16_split(v0,h0,l0); bf16_split(v1,h1,l1);
        size_t off = ((size_t)(b*4096) + px0+p)*1024 + ci0 + ci2;
        *(u32*)(xh+off) = pack_bf16(h0,h1);
        *(u32*)(xl+off) = pack_bf16(l0,l1);
    }
}

// ===================== weight prep: [co][ci][3][3] -> [t][chunk][co][ci%32] bf16 split ==========
__global__ void prep_w(const float* __restrict__ w, bf16* __restrict__ wh, bf16* __restrict__ wl,
                       int CIN, int CHUNKS, int total)
{
    int idx = blockIdx.x*256 + threadIdx.x;
    if (idx >= total) return;
    int i = idx & 31;
    int co = (idx>>5) & 255;
    int rest = idx >> 13;
    int c = rest % CHUNKS, t = rest / CHUNKS;
    float v = w[((size_t)co*CIN + c*32 + i)*9 + t];
    bf16 h,l; bf16_split(v,h,l);
    wh[idx] = h; wl[idx] = l;
}

// ===================== mma.sync bf16 implicit-GEMM 3x3 conv (3-product split) ============
// CTA: 128 px x 128 co, k-chunks of 32 ci per tap. 8 warps = 2(M) x 4(N), warp 64x32.
// Smem stage: A(hi|lo) 2x128x80B + B(hi|lo) 2x128x80B = 40960 B; double buffered.
constexpr int STG = 40960;

template <int CIN, bool TWO_IN, bool NHWC_OUT>
__global__ void __launch_bounds__(256) conv3x3_mma(
    const bf16* __restrict__ x0h, const bf16* __restrict__ x0l,
    const bf16* __restrict__ x1h, const bf16* __restrict__ x1l,
    const bf16* __restrict__ wh,  const bf16* __restrict__ wl,
    const float* __restrict__ bias,
    bf16* __restrict__ outh, bf16* __restrict__ outl, float* __restrict__ outf)
{
    constexpr int CH = CIN/32;
    constexpr int NITER = 9*CH;
    extern __shared__ char dsm[];
    __shared__ float s_bias[128];

    const int tid = threadIdx.x, wid = tid>>5, lane = tid&31;
    const int m0 = blockIdx.x*128;
    const int n0 = blockIdx.z*128;
    int b, inp = 0;
    if (TWO_IN) { b = blockIdx.y >> 1; inp = blockIdx.y & 1; } else b = blockIdx.y;
    const bf16* xh = (TWO_IN && inp) ? x1h : x0h;
    const bf16* xl = (TWO_IN && inp) ? x1l : x0l;
    const size_t bofs = (size_t)b * 4096;
    const int h0 = m0 >> 6;

    if (tid < 128) s_bias[tid] = bias[n0 + tid];
    __syncthreads();

    const u32 sm0 = smem_u32(dsm);

    // staging roles: 2 threads per row; half = hi/lo tile
    const int srow = tid >> 1, shalf = tid & 1;
    const int sr = srow >> 6, scol = srow & 63;

    auto stage = [&](int it){
        const int c = it / 9, t = it - 9*c;
        const u32 base = sm0 + (u32)(it & 1) * STG;
        // A: im2col row srow (px), 64B = 4x16B
        {
            const int hh = h0 + sr + (t/3) - 1;
            const int ww = scol + (t%3) - 1;
            const bool ok = ((unsigned)hh < 64u) && ((unsigned)ww < 64u);
            const bf16* src = (shalf ? xl : xh)
                + (ok ? ((bofs + (size_t)hh*64 + ww)*CIN + (size_t)c*32) : 0);
            const int sz = ok ? 16 : 0;
            u32 dst = base + shalf*10240 + srow*80;
            #pragma unroll
            for (int g = 0; g < 4; g++) CP_ASYNC_CA(dst + g*16, src + g*8, sz);
        }
        // B: weight row srow (co), 64B
        {
            const bf16* src = (shalf ? wl : wh)
                + ((size_t)((t*CH + c)*256 + n0 + srow)) * 32;
            u32 dst = base + 20480 + shalf*10240 + srow*80;
            #pragma unroll
            for (int g = 0; g < 4; g++) CP_ASYNC_CG(dst + g*16, src + g*8);
        }
        CP_COMMIT();
    };

    // compute-lane addressing
    const int wm = wid >> 2, wn = wid & 3;
    const u32 aoff = (u32)((wm*64 + (lane&15))*80 + (lane>>4)*16);
    const u32 boff = (u32)((wn*32 + (lane&7) + ((lane>>4)<<3))*80 + ((lane>>3)&1)*16);

    float acc[4][4][4];
    #pragma unroll
    for (int mf=0; mf<4; mf++)
        #pragma unroll
        for (int nf=0; nf<4; nf++)
            #pragma unroll
            for (int q=0; q<4; q++) acc[mf][nf][q] = 0.f;

    stage(0);
    for (int it = 0; it < NITER; ++it) {
        if (it + 1 < NITER) { stage(it + 1); CP_WAIT(1); }
        else CP_WAIT(0);
        __syncthreads();

        const u32 sA = sm0 + (u32)(it & 1) * STG;
        const u32 sB = sA + 20480;

        #pragma unroll
        for (int s = 0; s < 2; s++) {
            u32 a0[4][4], a1[4][4], bh[4][2], bl[4][2];
            #pragma unroll
            for (int mf = 0; mf < 4; mf++) {
                ldm_x4(a0[mf], sA + mf*1280 + s*32 + aoff);
                ldm_x4(a1[mf], sA + 10240 + mf*1280 + s*32 + aoff);
            }
            #pragma unroll
            for (int nfp = 0; nfp < 2; nfp++) {
                u32 r[4];
                ldm_x4(r, sB + nfp*1280 + s*32 + boff);
                bh[nfp*2][0]=r[0]; bh[nfp*2][1]=r[1]; bh[nfp*2+1][0]=r[2]; bh[nfp*2+1][1]=r[3];
                ldm_x4(r, sB + 10240 + nfp*1280 + s*32 + boff);
                bl[nfp*2][0]=r[0]; bl[nfp*2][1]=r[1]; bl[nfp*2+1][0]=r[2]; bl[nfp*2+1][1]=r[3];
            }
            #pragma unroll
            for (int mf = 0; mf < 4; mf++)
                #pragma unroll
                for (int nf = 0; nf < 4; nf++) mma_bf16(acc[mf][nf], a0[mf], bh[nf]);
            #pragma unroll
            for (int mf = 0; mf < 4; mf++)
                #pragma unroll
                for (int nf = 0; nf < 4; nf++) mma_bf16(acc[mf][nf], a1[mf], bh[nf]);
            #pragma unroll
            for (int mf = 0; mf < 4; mf++)
                #pragma unroll
                for (int nf = 0; nf < 4; nf++) mma_bf16(acc[mf][nf], a0[mf], bl[nf]);
        }
        __syncthreads();
    }

    // epilogue
    #pragma unroll
    for (int mf = 0; mf < 4; mf++) {
        #pragma unroll
        for (int nf = 0; nf < 4; nf++) {
            const int co = n0 + wn*32 + nf*8 + 2*(lane&3);
            const float bv0 = s_bias[co - n0], bv1 = s_bias[co - n0 + 1];
            #pragma unroll
            for (int h2 = 0; h2 < 2; h2++) {
                const int m = m0 + wm*64 + mf*16 + (lane>>2) + h2*8;
                float v0 = fmaxf(acc[mf][nf][h2*2+0] + bv0, 0.f);
                float v1 = fmaxf(acc[mf][nf][h2*2+1] + bv1, 0.f);
                if (NHWC_OUT) {
                    bf16 h0_,l0_,h1_,l1_;
                    bf16_split(v0,h0_,l0_); bf16_split(v1,h1_,l1_);
                    size_t off = (bofs + m)*512 + inp*256 + co;
                    *(u32*)(outh+off) = pack_bf16(h0_,h1_);
                    *(u32*)(outl+off) = pack_bf16(l0_,l1_);
                } else {
                    outf[((size_t)(b*256 + co))*4096 + m]     = v0;
                    outf[((size_t)(b*256 + co + 1))*4096 + m] = v1;
                }
            }
        }
    }
}

// ===================== 1x1 conv (256->81) + relu + softmax =====================
__global__ void __launch_bounds__(256) conv1x1_softmax_kernel(
    const float* __restrict__ x2, const float* __restrict__ w3,
    const float* __restrict__ b3, float* __restrict__ kout)
{
    __shared__ float s_w[81*64];
    __shared__ float s_logit[81*64];
    __shared__ float s_m[64], s_r[64];
    const int tid = threadIdx.x, px = tid & 63, grp = tid >> 6;
    const int h = blockIdx.x, b = blockIdx.y;

    float acc[21];
    #pragma unroll
    for (int k = 0; k < 21; k++) { int co = grp + 4*k; acc[k] = (co < 81) ? b3[co] : 0.f; }
    const float* xb = x2 + ((size_t)b*256)*4096 + h*64 + px;

    for (int ci0 = 0; ci0 < 256; ci0 += 64) {
        __syncthreads();
        for (int j = tid; j < 81*64; j += 256) s_w[j] = w3[(j>>6)*256 + ci0 + (j&63)];
        __syncthreads();
        for (int i = 0; i < 64; i++) {
            float xv = __ldg(xb + (size_t)(ci0 + i)*4096);
            #pragma unroll
            for (int k = 0; k < 21; k++) { int co = grp + 4*k; if (co < 81) acc[k] += xv * s_w[co*64 + i]; }
        }
    }
    #pragma unroll
    for (int k = 0; k < 21; k++) { int co = grp + 4*k; if (co < 81) s_logit[co*64 + px] = fmaxf(acc[k], 0.f); }
    __syncthreads();
    if (tid < 64) {
        float m = -1e30f;
        for (int co = 0; co < 81; co++) m = fmaxf(m, s_logit[co*64 + tid]);
        float s = 0.f;
        for (int co = 0; co < 81; co++) s += __expf(s_logit[co*64 + tid] - m);
        s_m[tid] = m; s_r[tid] = 1.f / s;
    }
    __syncthreads();
    float m = s_m[px], rr = s_r[px];
    #pragma unroll
    for (int k = 0; k < 21; k++) {
        int co = grp + 4*k;
        if (co < 81)
            kout[((size_t)(b*81 + co)*4096) + h*64 + px] = __expf(s_logit[co*64 + px] - m) * rr;
    }
}

// ===================== spatially-variant 9x9 conv =====================
__global__ void __launch_bounds__(256) svc_kernel(
    const float* __restrict__ feats, const float* __restrict__ kern, float* __restrict__ out)
{
    __shared__ float k_s[81*64];
    __shared__ float f_s[16*16*24];
    const int tid = threadIdx.x;
    const int px_x = tid & 7, py = (tid>>3) & 7, cq = tid >> 6;
    const int px = py*8 + px_x;
    const int w0 = blockIdx.x*8, h0 = blockIdx.y*8;
    const int b = blockIdx.z >> 6, cbase = (blockIdx.z & 63) * 16;

    for (int j = tid; j < 81*64; j += 256) {
        int idx = j>>6, p = j&63;
        k_s[j] = kern[((size_t)(b*81 + idx)*64 + h0 + (p>>3))*64 + w0 + (p&7)];
    }
    for (int j = tid; j < 16*16*16; j += 256) {
        int c = j>>8, rw = (j>>4)&15, cl = j&15;
        int gr = h0 + rw - 4, gc = w0 + cl - 4;
        float v = 0.f;
        if ((unsigned)gr < 64u && (unsigned)gc < 64u)
            v = feats[((size_t)(b*1024 + cbase + c))*4096 + gr*64 + gc];
        f_s[c*384 + rw*24 + cl] = v;
    }
    __syncthreads();

    float acc[4] = {0.f,0.f,0.f,0.f};
    #pragma unroll 1
    for (int i = 0; i < 9; i++) {
        const int fb = (py+i)*24 + px_x + (cq*4)*384;
        #pragma unroll
        for (int j = 0; j < 9; j++) {
            float kv = k_s[(i*9 + j)*64 + px];
            #pragma unroll
            for (int c = 0; c < 4; c++) acc[c] += f_s[fb + j + c*384] * kv;
        }
    }
    size_t ob = ((size_t)(b*1024 + cbase + cq*4))*4096 + (size_t)(h0+py)*64 + w0 + px_x;
    #pragma unroll
    for (int c = 0; c < 4; c++) out[ob + (size_t)c*4096] = acc[c];
}

// ===================== launch =====================
extern "C" void kernel_launch(void* const* d_in, const int* in_sizes, int n_in,
                              void* d_out, int out_size)
{
    (void)in_sizes; (void)n_in; (void)out_size;
    const float* cur  = (const float*)d_in[0];
    const float* keyl = (const float*)d_in[1];
    const float* high = (const float*)d_in[2];
    const float* w1   = (const float*)d_in[3];
    const float* b1   = (const float*)d_in[4];
    const float* w2   = (const float*)d_in[5];
    const float* b2   = (const float*)d_in[6];
    const float* w3   = (const float*)d_in[7];
    const float* b3   = (const float*)d_in[8];
    float* out = (float*)d_out;

    bf16 *x0h,*x0l,*x1h,*x1l,*w1h,*w1l,*w2h,*w2l,*b1h,*b1l;
    float *buf2,*kern;
    cudaGetSymbolAddress((void**)&x0h, g_x0h);
    cudaGetSymbolAddress((void**)&x0l, g_x0l);
    cudaGetSymbolAddress((void**)&x1h, g_x1h);
    cudaGetSymbolAddress((void**)&x1l, g_x1l);
    cudaGetSymbolAddress((void**)&w1h, g_w1h);
    cudaGetSymbolAddress((void**)&w1l, g_w1l);
    cudaGetSymbolAddress((void**)&w2h, g_w2h);
    cudaGetSymbolAddress((void**)&w2l, g_w2l);
    cudaGetSymbolAddress((void**)&b1h, g_b1h);
    cudaGetSymbolAddress((void**)&b1l, g_b1l);
    cudaGetSymbolAddress((void**)&buf2, g_buf2);
    cudaGetSymbolAddress((void**)&kern, g_kern);

    const int DSM = 2*STG;
    cudaFuncSetAttribute(conv3x3_mma<1024,true,true>,  cudaFuncAttributeMaxDynamicSharedMemorySize, DSM);
    cudaFuncSetAttribute(conv3x3_mma<512,false,false>, cudaFuncAttributeMaxDynamicSharedMemorySize, DSM);

    transpose_split<<<dim3(64,16,4), 256>>>(cur,  x0h, x0l);
    transpose_split<<<dim3(64,16,4), 256>>>(keyl, x1h, x1l);
    prep_w<<<(9*32*8192+255)/256, 256>>>(w1, w1h, w1l, 1024, 32, 9*32*8192);
    prep_w<<<(9*16*8192+255)/256, 256>>>(w2, w2h, w2l, 512, 16, 9*16*8192);

    conv3x3_mma<1024,true,true><<<dim3(32,8,2), 256, DSM>>>(
        x0h, x0l, x1h, x1l, w1h, w1l, b1, b1h, b1l, nullptr);
    conv3x3_mma<512,false,false><<<dim3(32,4,2), 256, DSM>>>(
        b1h, b1l, nullptr, nullptr, w2h, w2l, b2, nullptr, nullptr, buf2);

    conv1x1_softmax_kernel<<<dim3(64,4), 256>>>(buf2, w3, b3, kern);
    svc_kernel<<<dim3(8,8,256), 256>>>(high, kern, out);
}

// round 5
// speedup vs baseline: 1.9181x; 1.0491x over previous
#include <cuda_runtime.h>
#include <cuda_bf16.h>
#include <cstdint>

typedef unsigned u32; typedef unsigned long long u64;
typedef __nv_bfloat16 bf16;

// ===================== PTX helpers (portable: sm_80-class only) =====================
__device__ __forceinline__ u32 smem_u32(const void* p){
    u32 a; asm("{ .reg .u64 t; cvta.to.shared.u64 t, %1; cvt.u32.u64 %0, t; }":"=r"(a):"l"(p)); return a;
}
#define CP_ASYNC_CA(dst, src, sz) \
    asm volatile("cp.async.ca.shared.global [%0], [%1], 16, %2;" :: "r"(dst), "l"(src), "r"(sz))
#define CP_ASYNC_CG(dst, src) \
    asm volatile("cp.async.cg.shared.global [%0], [%1], 16;" :: "r"(dst), "l"(src))
#define CP_COMMIT() asm volatile("cp.async.commit_group;" ::: "memory")
#define CP_WAIT(N)  asm volatile("cp.async.wait_group %0;" :: "n"(N) : "memory")

__device__ __forceinline__ void ldm_x4(u32* r, u32 addr){
    asm volatile("ldmatrix.sync.aligned.m8n8.x4.shared.b16 {%0,%1,%2,%3}, [%4];"
        : "=r"(r[0]),"=r"(r[1]),"=r"(r[2]),"=r"(r[3]) : "r"(addr));
}
__device__ __forceinline__ void mma_bf16(float* c, const u32* a, const u32* b){
    asm volatile("mma.sync.aligned.m16n8k16.row.col.f32.bf16.bf16.f32 "
        "{%0,%1,%2,%3}, {%4,%5,%6,%7}, {%8,%9}, {%0,%1,%2,%3};"
        : "+f"(c[0]),"+f"(c[1]),"+f"(c[2]),"+f"(c[3])
        : "r"(a[0]),"r"(a[1]),"r"(a[2]),"r"(a[3]), "r"(b[0]),"r"(b[1]));
}
__device__ __forceinline__ void bf16_split(float v, bf16& h, bf16& l){
    h = __float2bfloat16(v);
    l = __float2bfloat16(v - __bfloat162float(h));
}
__device__ __forceinline__ u32 pack_bf16(bf16 a, bf16 b){
    return (u32)__bfloat16_as_ushort(a) | ((u32)__bfloat16_as_ushort(b) << 16);
}

// ===================== device scratch =====================
__device__ bf16 g_x0h[4ULL*4096*1024];
__device__ bf16 g_x0l[4ULL*4096*1024];
__device__ bf16 g_x1h[4ULL*4096*1024];
__device__ bf16 g_x1l[4ULL*4096*1024];
__device__ bf16 g_w1h[9*32*256*32];
__device__ bf16 g_w1l[9*32*256*32];
__device__ bf16 g_w2h[9*16*256*32];
__device__ bf16 g_w2l[9*16*256*32];
__device__ bf16 g_b1h[4ULL*4096*512];   // NHWC bf16-hi of concat(cur,key) conv1 output
__device__ bf16 g_b1l[4ULL*4096*512];
__device__ float g_buf2[4ULL*256*4096]; // NCHW conv2 output
__device__ float g_kern[4ULL*81*4096];  // NCHW softmax kernels

// ===================== NCHW fp32 -> NHWC bf16 hi/lo (C=1024) =====================
__global__ void __launch_bounds__(256) transpose_split(
    const float* __restrict__ x, bf16* __restrict__ xh, bf16* __restrict__ xl)
{
    __shared__ float s[64*65];
    const int tid = threadIdx.x, px0 = blockIdx.x*64, ci0 = blockIdx.y*64, b = blockIdx.z;
    for (int j = tid; j < 4096; j += 256){
        int ci = j>>6, p = j&63;
        s[ci*65+p] = x[((size_t)(b*1024 + ci0+ci))*4096 + px0 + p];
    }
    __syncthreads();
    for (int j = tid; j < 2048; j += 256){
        int p = j>>5, ci2 = (j&31)*2;
        float v0 = s[ci2*65+p], v1 = s[(ci2+1)*65+p];
        bf16 h0,l0,h1,l1; bf16_split(v0,h0,l0); bf16_split(v1,h1,l1);
        size_t off = ((size_t)(b*4096) + px0+p)*1024 + ci0 + ci2;
        *(u32*)(xh+off) = pack_bf16(h0,h1);
        *(u32*)(xl+off) = pack_bf16(l0,l1);
    }
}

// ===================== weight prep: [co][ci][3][3] -> [t][chunk][co][ci%32] bf16 split ==========
__global__ void prep_w(const float* __restrict__ w, bf16* __restrict__ wh, bf16* __restrict__ wl,
                       int CIN, int CHUNKS, int total)
{
    int idx = blockIdx.x*256 + threadIdx.x;
    if (idx >= total) return;
    int i = idx & 31;
    int co = (idx>>5) & 255;
    int rest = idx >> 13;
    int c = rest % CHUNKS, t = rest / CHUNKS;
    float v = w[((size_t)co*CIN + c*32 + i)*9 + t];
    bf16 h,l; bf16_split(v,h,l);
    wh[idx] = h; wl[idx] = l;
}

// ===================== mma.sync bf16 implicit-GEMM 3x3 conv (3-product split) ============
// CTA: 128 px x 256 co, k-chunks of 32 ci per tap. 8 warps = 2(M) x 4(N), warp 64x64.
// Stage: A(hi|lo) 2x128x80B + B(hi|lo) 2x256x80B = 61440 B; 3-stage cp.async pipeline.
constexpr int STG = 61440;
constexpr int NSTG = 3;

template <int CIN, bool TWO_IN, bool NHWC_OUT>
__global__ void __launch_bounds__(256, 1) conv3x3_mma(
    const bf16* __restrict__ x0h, const bf16* __restrict__ x0l,
    const bf16* __restrict__ x1h, const bf16* __restrict__ x1l,
    const bf16* __restrict__ wh,  const bf16* __restrict__ wl,
    const float* __restrict__ bias,
    bf16* __restrict__ outh, bf16* __restrict__ outl, float* __restrict__ outf)
{
    constexpr int CH = CIN/32;
    constexpr int NITER = 9*CH;
    extern __shared__ char dsm[];
    __shared__ float s_bias[256];

    const int tid = threadIdx.x, wid = tid>>5, lane = tid&31;
    const int m0 = blockIdx.x*128;
    int b, inp = 0;
    if (TWO_IN) { b = blockIdx.y >> 1; inp = blockIdx.y & 1; } else b = blockIdx.y;
    const bf16* xh = (TWO_IN && inp) ? x1h : x0h;
    const bf16* xl = (TWO_IN && inp) ? x1l : x0l;
    const size_t bofs = (size_t)b * 4096;
    const int h0 = m0 >> 6;

    s_bias[tid] = bias[tid];
    __syncthreads();

    const u32 sm0 = smem_u32(dsm);

    // staging roles
    const int arow = tid >> 1, ahalf = tid & 1;          // A: 128 rows x 2 halves
    const int ar = arow >> 6, acol = arow & 63;

    auto stage = [&](int it){
        const int c = it / 9, t = it - 9*c;
        const u32 base = sm0 + (u32)(it % NSTG) * STG;
        // A: im2col row arow (px), 64B = 4x16B
        {
            const int hh = h0 + ar + (t/3) - 1;
            const int ww = acol + (t%3) - 1;
            const bool ok = ((unsigned)hh < 64u) && ((unsigned)ww < 64u);
            const bf16* src = (ahalf ? xl : xh)
                + (ok ? ((bofs + (size_t)hh*64 + ww)*CIN + (size_t)c*32) : 0);
            const int sz = ok ? 16 : 0;
            u32 dst = base + ahalf*10240 + arow*80;
            #pragma unroll
            for (int g = 0; g < 4; g++) CP_ASYNC_CA(dst + g*16, src + g*8, sz);
        }
        // B: 256 co rows x 2 halves = 512 tasks, 2 per thread
        #pragma unroll
        for (int t2 = 0; t2 < 2; t2++) {
            const int idx = tid + t2*256;
            const int brow = idx >> 1, bhalf = idx & 1;
            const bf16* src = (bhalf ? wl : wh)
                + ((size_t)((t*CH + c)*256 + brow)) * 32;
            u32 dst = base + 20480 + bhalf*20480 + brow*80;
            #pragma unroll
            for (int g = 0; g < 4; g++) CP_ASYNC_CG(dst + g*16, src + g*8);
        }
        CP_COMMIT();
    };

    // compute-lane addressing: warp = (wm in 0..1) x (wn in 0..3), tile 64px x 64co
    const int wm = wid >> 2, wn = wid & 3;
    const u32 aoff = (u32)((wm*64 + (lane&15))*80 + (lane>>4)*16);
    const u32 boff = (u32)((wn*64 + (lane&7) + ((lane>>4)<<3))*80 + ((lane>>3)&1)*16);

    float acc[4][8][4];
    #pragma unroll
    for (int mf=0; mf<4; mf++)
        #pragma unroll
        for (int nf=0; nf<8; nf++)
            #pragma unroll
            for (int q=0; q<4; q++) acc[mf][nf][q] = 0.f;

    stage(0);
    stage(1);
    for (int it = 0; it < NITER; ++it) {
        if (it + 2 < NITER) stage(it + 2); else CP_COMMIT();
        CP_WAIT(2);
        __syncthreads();

        const u32 sA = sm0 + (u32)(it % NSTG) * STG;
        const u32 sB = sA + 20480;

        #pragma unroll
        for (int s = 0; s < 2; s++) {
            u32 a0[4][4], a1[4][4];
            #pragma unroll
            for (int mf = 0; mf < 4; mf++) {
                ldm_x4(a0[mf], sA + mf*1280 + s*32 + aoff);
                ldm_x4(a1[mf], sA + 10240 + mf*1280 + s*32 + aoff);
            }
            #pragma unroll
            for (int nfp = 0; nfp < 4; nfp++) {
                u32 rh[4], rl[4];
                ldm_x4(rh, sB + nfp*1280 + s*32 + boff);
                ldm_x4(rl, sB + 20480 + nfp*1280 + s*32 + boff);
                u32 bh0[2] = {rh[0], rh[1]}, bh1[2] = {rh[2], rh[3]};
                u32 bl0[2] = {rl[0], rl[1]}, bl1[2] = {rl[2], rl[3]};
                #pragma unroll
                for (int mf = 0; mf < 4; mf++) {
                    mma_bf16(acc[mf][nfp*2],   a0[mf], bh0);
                    mma_bf16(acc[mf][nfp*2+1], a0[mf], bh1);
                }
                #pragma unroll
                for (int mf = 0; mf < 4; mf++) {
                    mma_bf16(acc[mf][nfp*2],   a1[mf], bh0);
                    mma_bf16(acc[mf][nfp*2+1], a1[mf], bh1);
                }
                #pragma unroll
                for (int mf = 0; mf < 4; mf++) {
                    mma_bf16(acc[mf][nfp*2],   a0[mf], bl0);
                    mma_bf16(acc[mf][nfp*2+1], a0[mf], bl1);
                }
            }
        }
        __syncthreads();
    }

    // epilogue: warp covers 64px x 64co
    #pragma unroll
    for (int mf = 0; mf < 4; mf++) {
        #pragma unroll
        for (int nf = 0; nf < 8; nf++) {
            const int co = wn*64 + nf*8 + 2*(lane&3);
            const float bv0 = s_bias[co], bv1 = s_bias[co + 1];
            #pragma unroll
            for (int h2 = 0; h2 < 2; h2++) {
                const int m = m0 + wm*64 + mf*16 + (lane>>2) + h2*8;
                float v0 = fmaxf(acc[mf][nf][h2*2+0] + bv0, 0.f);
                float v1 = fmaxf(acc[mf][nf][h2*2+1] + bv1, 0.f);
                if (NHWC_OUT) {
                    bf16 h0_,l0_,h1_,l1_;
                    bf16_split(v0,h0_,l0_); bf16_split(v1,h1_,l1_);
                    size_t off = (bofs + m)*512 + inp*256 + co;
                    *(u32*)(outh+off) = pack_bf16(h0_,h1_);
                    *(u32*)(outl+off) = pack_bf16(l0_,l1_);
                } else {
                    outf[((size_t)(b*256 + co))*4096 + m]     = v0;
                    outf[((size_t)(b*256 + co + 1))*4096 + m] = v1;
                }
            }
        }
    }
}

// ===================== 1x1 conv (256->81) + relu + softmax =====================
__global__ void __launch_bounds__(256) conv1x1_softmax_kernel(
    const float* __restrict__ x2, const float* __restrict__ w3,
    const float* __restrict__ b3, float* __restrict__ kout)
{
    __shared__ float s_w[81*64];
    __shared__ float s_logit[81*64];
    __shared__ float s_m[64], s_r[64];
    const int tid = threadIdx.x, px = tid & 63, grp = tid >> 6;
    const int h = blockIdx.x, b = blockIdx.y;

    float acc[21];
    #pragma unroll
    for (int k = 0; k < 21; k++) { int co = grp + 4*k; acc[k] = (co < 81) ? b3[co] : 0.f; }
    const float* xb = x2 + ((size_t)b*256)*4096 + h*64 + px;

    for (int ci0 = 0; ci0 < 256; ci0 += 64) {
        __syncthreads();
        for (int j = tid; j < 81*64; j += 256) s_w[j] = w3[(j>>6)*256 + ci0 + (j&63)];
        __syncthreads();
        for (int i = 0; i < 64; i++) {
            float xv = __ldg(xb + (size_t)(ci0 + i)*4096);
            #pragma unroll
            for (int k = 0; k < 21; k++) { int co = grp + 4*k; if (co < 81) acc[k] += xv * s_w[co*64 + i]; }
        }
    }
    #pragma unroll
    for (int k = 0; k < 21; k++) { int co = grp + 4*k; if (co < 81) s_logit[co*64 + px] = fmaxf(acc[k], 0.f); }
    __syncthreads();
    if (tid < 64) {
        float m = -1e30f;
        for (int co = 0; co < 81; co++) m = fmaxf(m, s_logit[co*64 + tid]);
        float s = 0.f;
        for (int co = 0; co < 81; co++) s += __expf(s_logit[co*64 + tid] - m);
        s_m[tid] = m; s_r[tid] = 1.f / s;
    }
    __syncthreads();
    float m = s_m[px], rr = s_r[px];
    #pragma unroll
    for (int k = 0; k < 21; k++) {
        int co = grp + 4*k;
        if (co < 81)
            kout[((size_t)(b*81 + co)*4096) + h*64 + px] = __expf(s_logit[co*64 + px] - m) * rr;
    }
}

// ===================== spatially-variant 9x9 conv =====================
__global__ void __launch_bounds__(256) svc_kernel(
    const float* __restrict__ feats, const float* __restrict__ kern, float* __restrict__ out)
{
    __shared__ float k_s[81*64];
    __shared__ float f_s[16*16*24];
    const int tid = threadIdx.x;
    const int px_x = tid & 7, py = (tid>>3) & 7, cq = tid >> 6;
    const int px = py*8 + px_x;
    const int w0 = blockIdx.x*8, h0 = blockIdx.y*8;
    const int b = blockIdx.z >> 6, cbase = (blockIdx.z & 63) * 16;

    for (int j = tid; j < 81*64; j += 256) {
        int idx = j>>6, p = j&63;
        k_s[j] = kern[((size_t)(b*81 + idx)*64 + h0 + (p>>3))*64 + w0 + (p&7)];
    }
    for (int j = tid; j < 16*16*16; j += 256) {
        int c = j>>8, rw = (j>>4)&15, cl = j&15;
        int gr = h0 + rw - 4, gc = w0 + cl - 4;
        float v = 0.f;
        if ((unsigned)gr < 64u && (unsigned)gc < 64u)
            v = feats[((size_t)(b*1024 + cbase + c))*4096 + gr*64 + gc];
        f_s[c*384 + rw*24 + cl] = v;
    }
    __syncthreads();

    float acc[4] = {0.f,0.f,0.f,0.f};
    #pragma unroll 1
    for (int i = 0; i < 9; i++) {
        const int fb = (py+i)*24 + px_x + (cq*4)*384;
        #pragma unroll
        for (int j = 0; j < 9; j++) {
            float kv = k_s[(i*9 + j)*64 + px];
            #pragma unroll
            for (int c = 0; c < 4; c++) acc[c] += f_s[fb + j + c*384] * kv;
        }
    }
    size_t ob = ((size_t)(b*1024 + cbase + cq*4))*4096 + (size_t)(h0+py)*64 + w0 + px_x;
    #pragma unroll
    for (int c = 0; c < 4; c++) out[ob + (size_t)c*4096] = acc[c];
}

// ===================== launch =====================
extern "C" void kernel_launch(void* const* d_in, const int* in_sizes, int n_in,
                              void* d_out, int out_size)
{
    (void)in_sizes; (void)n_in; (void)out_size;
    const float* cur  = (const float*)d_in[0];
    const float* keyl = (const float*)d_in[1];
    const float* high = (const float*)d_in[2];
    const float* w1   = (const float*)d_in[3];
    const float* b1   = (const float*)d_in[4];
    const float* w2   = (const float*)d_in[5];
    const float* b2   = (const float*)d_in[6];
    const float* w3   = (const float*)d_in[7];
    const float* b3   = (const float*)d_in[8];
    float* out = (float*)d_out;

    bf16 *x0h,*x0l,*x1h,*x1l,*w1h,*w1l,*w2h,*w2l,*b1h,*b1l;
    float *buf2,*kern;
    cudaGetSymbolAddress((void**)&x0h, g_x0h);
    cudaGetSymbolAddress((void**)&x0l, g_x0l);
    cudaGetSymbolAddress((void**)&x1h, g_x1h);
    cudaGetSymbolAddress((void**)&x1l, g_x1l);
    cudaGetSymbolAddress((void**)&w1h, g_w1h);
    cudaGetSymbolAddress((void**)&w1l, g_w1l);
    cudaGetSymbolAddress((void**)&w2h, g_w2h);
    cudaGetSymbolAddress((void**)&w2l, g_w2l);
    cudaGetSymbolAddress((void**)&b1h, g_b1h);
    cudaGetSymbolAddress((void**)&b1l, g_b1l);
    cudaGetSymbolAddress((void**)&buf2, g_buf2);
    cudaGetSymbolAddress((void**)&kern, g_kern);

    const int DSM = NSTG*STG;
    cudaFuncSetAttribute(conv3x3_mma<1024,true,true>,  cudaFuncAttributeMaxDynamicSharedMemorySize, DSM);
    cudaFuncSetAttribute(conv3x3_mma<512,false,false>, cudaFuncAttributeMaxDynamicSharedMemorySize, DSM);

    transpose_split<<<dim3(64,16,4), 256>>>(cur,  x0h, x0l);
    transpose_split<<<dim3(64,16,4), 256>>>(keyl, x1h, x1l);
    prep_w<<<(9*32*8192+255)/256, 256>>>(w1, w1h, w1l, 1024, 32, 9*32*8192);
    prep_w<<<(9*16*8192+255)/256, 256>>>(w2, w2h, w2l, 512, 16, 9*16*8192);

    conv3x3_mma<1024,true,true><<<dim3(32,8), 256, DSM>>>(
        x0h, x0l, x1h, x1l, w1h, w1l, b1, b1h, b1l, nullptr);
    conv3x3_mma<512,false,false><<<dim3(32,4), 256, DSM>>>(
        b1h, b1l, nullptr, nullptr, w2h, w2l, b2, nullptr, nullptr, buf2);

    conv1x1_softmax_kernel<<<dim3(64,4), 256>>>(buf2, w3, b3, kern);
    svc_kernel<<<dim3(8,8,256), 256>>>(high, kern, out);
}

// round 6
// speedup vs baseline: 1.9983x; 1.0418x over previous
#include <cuda_runtime.h>
#include <cuda_bf16.h>
#include <cstdint>

typedef unsigned u32; typedef unsigned long long u64;
typedef __nv_bfloat16 bf16;

// ===================== PTX helpers (portable: sm_80-class only) =====================
__device__ __forceinline__ u32 smem_u32(const void* p){
    u32 a; asm("{ .reg .u64 t; cvta.to.shared.u64 t, %1; cvt.u32.u64 %0, t; }":"=r"(a):"l"(p)); return a;
}
#define CP_ASYNC_CA(dst, src, sz) \
    asm volatile("cp.async.ca.shared.global [%0], [%1], 16, %2;" :: "r"(dst), "l"(src), "r"(sz))
#define CP_ASYNC_CG(dst, src) \
    asm volatile("cp.async.cg.shared.global [%0], [%1], 16;" :: "r"(dst), "l"(src))
#define CP_COMMIT() asm volatile("cp.async.commit_group;" ::: "memory")
#define CP_WAIT(N)  asm volatile("cp.async.wait_group %0;" :: "n"(N) : "memory")

__device__ __forceinline__ void ldm_x4(u32* r, u32 addr){
    asm volatile("ldmatrix.sync.aligned.m8n8.x4.shared.b16 {%0,%1,%2,%3}, [%4];"
        : "=r"(r[0]),"=r"(r[1]),"=r"(r[2]),"=r"(r[3]) : "r"(addr));
}
__device__ __forceinline__ void mma_bf16(float* c, const u32* a, const u32* b){
    asm volatile("mma.sync.aligned.m16n8k16.row.col.f32.bf16.bf16.f32 "
        "{%0,%1,%2,%3}, {%4,%5,%6,%7}, {%8,%9}, {%0,%1,%2,%3};"
        : "+f"(c[0]),"+f"(c[1]),"+f"(c[2]),"+f"(c[3])
        : "r"(a[0]),"r"(a[1]),"r"(a[2]),"r"(a[3]), "r"(b[0]),"r"(b[1]));
}
__device__ __forceinline__ void bf16_split(float v, bf16& h, bf16& l){
    h = __float2bfloat16(v);
    l = __float2bfloat16(v - __bfloat162float(h));
}
__device__ __forceinline__ u32 pack_bf16(bf16 a, bf16 b){
    return (u32)__bfloat16_as_ushort(a) | ((u32)__bfloat16_as_ushort(b) << 16);
}

// ===================== device scratch =====================
__device__ bf16 g_x0h[4ULL*4096*1024];
__device__ bf16 g_x0l[4ULL*4096*1024];
__device__ bf16 g_x1h[4ULL*4096*1024];
__device__ bf16 g_x1l[4ULL*4096*1024];
__device__ bf16 g_w1h[9*32*256*32];
__device__ bf16 g_w1l[9*32*256*32];
__device__ bf16 g_w2h[9*16*256*32];
__device__ bf16 g_w2l[9*16*256*32];
__device__ bf16 g_b1h[4ULL*4096*512];   // NHWC bf16-hi of concat(cur,key) conv1 output
__device__ bf16 g_b1l[4ULL*4096*512];
__device__ float g_buf2[4ULL*256*4096]; // NCHW conv2 output
__device__ float g_kern[4ULL*81*4096];  // NCHW softmax kernels

// ===================== NCHW fp32 -> NHWC bf16 hi/lo (C=1024) =====================
__global__ void __launch_bounds__(256) transpose_split(
    const float* __restrict__ x, bf16* __restrict__ xh, bf16* __restrict__ xl)
{
    __shared__ float s[64*65];
    const int tid = threadIdx.x, px0 = blockIdx.x*64, ci0 = blockIdx.y*64, b = blockIdx.z;
    for (int j = tid; j < 4096; j += 256){
        int ci = j>>6, p = j&63;
        s[ci*65+p] = x[((size_t)(b*1024 + ci0+ci))*4096 + px0 + p];
    }
    __syncthreads();
    for (int j = tid; j < 2048; j += 256){
        int p = j>>5, ci2 = (j&31)*2;
        float v0 = s[ci2*65+p], v1 = s[(ci2+1)*65+p];
        bf16 h0,l0,h1,l1; bf16_split(v0,h0,l0); bf16_split(v1,h1,l1);
        size_t off = ((size_t)(b*4096) + px0+p)*1024 + ci0 + ci2;
        *(u32*)(xh+off) = pack_bf16(h0,h1);
        *(u32*)(xl+off) = pack_bf16(l0,l1);
    }
}

// ===================== weight prep: [co][ci][3][3] -> [t][chunk][co][ci%32] bf16 split ==========
__global__ void prep_w(const float* __restrict__ w, bf16* __restrict__ wh, bf16* __restrict__ wl,
                       int CIN, int CHUNKS, int total)
{
    int idx = blockIdx.x*256 + threadIdx.x;
    if (idx >= total) return;
    int i = idx & 31;
    int co = (idx>>5) & 255;
    int rest = idx >> 13;
    int c = rest % CHUNKS, t = rest / CHUNKS;
    float v = w[((size_t)co*CIN + c*32 + i)*9 + t];
    bf16 h,l; bf16_split(v,h,l);
    wh[idx] = h; wl[idx] = l;
}

// ===================== mma.sync bf16 implicit-GEMM 3x3 conv (3-product split) ============
// CTA: 128 px x 256 co, k-chunks of 32 ci per tap. 16 warps = 4(M) x 4(N), warp 32x64.
// Stage: A(hi|lo) 2x128x80B + B(hi|lo) 2x256x80B = 61440 B; 3-stage cp.async pipeline.
constexpr int STG = 61440;
constexpr int NSTG = 3;

template <int CIN, bool TWO_IN, bool NHWC_OUT>
__global__ void __launch_bounds__(512, 1) conv3x3_mma(
    const bf16* __restrict__ x0h, const bf16* __restrict__ x0l,
    const bf16* __restrict__ x1h, const bf16* __restrict__ x1l,
    const bf16* __restrict__ wh,  const bf16* __restrict__ wl,
    const float* __restrict__ bias,
    bf16* __restrict__ outh, bf16* __restrict__ outl, float* __restrict__ outf)
{
    constexpr int CH = CIN/32;
    constexpr int NITER = 9*CH;
    extern __shared__ char dsm[];
    __shared__ float s_bias[256];

    const int tid = threadIdx.x, wid = tid>>5, lane = tid&31;
    const int m0 = blockIdx.x*128;
    int b, inp = 0;
    if (TWO_IN) { b = blockIdx.y >> 1; inp = blockIdx.y & 1; } else b = blockIdx.y;
    const bf16* xh = (TWO_IN && inp) ? x1h : x0h;
    const bf16* xl = (TWO_IN && inp) ? x1l : x0l;
    const size_t bofs = (size_t)b * 4096;
    const int h0 = m0 >> 6;

    if (tid < 256) s_bias[tid] = bias[tid];
    __syncthreads();

    const u32 sm0 = smem_u32(dsm);

    // --- staging roles ---
    // A: 128 px-rows x 2 halves = 256 units of 64B; thread pair covers one unit (32B each)
    const int au = tid >> 1;                 // 0..255
    const int arow = au >> 1, ahalf = au & 1;
    const int ar = arow >> 6, acol = arow & 63;
    const int asub = (tid & 1) * 32;         // byte offset within 64B row
    // B: 256 co-rows x 2 halves = 512 units of 64B; one unit per thread
    const int brow = tid >> 1, bhalf = tid & 1;

    auto stage = [&](int it){
        const int c = it / 9, t = it - 9*c;
        const u32 base = sm0 + (u32)(it % NSTG) * STG;
        // A: im2col row arow (px)
        {
            const int hh = h0 + ar + (t/3) - 1;
            const int ww = acol + (t%3) - 1;
            const bool ok = ((unsigned)hh < 64u) && ((unsigned)ww < 64u);
            const bf16* src = (ahalf ? xl : xh)
                + (ok ? ((bofs + (size_t)hh*64 + ww)*CIN + (size_t)c*32) : 0)
                + asub/2;
            const int sz = ok ? 16 : 0;
            u32 dst = base + ahalf*10240 + arow*80 + asub;
            CP_ASYNC_CA(dst,      src,     sz);
            CP_ASYNC_CA(dst + 16, src + 8, sz);
        }
        // B: weight row brow (co), 64B
        {
            const bf16* src = (bhalf ? wl : wh)
                + ((size_t)((t*CH + c)*256 + brow)) * 32;
            u32 dst = base + 20480 + bhalf*20480 + brow*80;
            #pragma unroll
            for (int g = 0; g < 4; g++) CP_ASYNC_CG(dst + g*16, src + g*8);
        }
        CP_COMMIT();
    };

    // compute-lane addressing: warp = (wm 0..3) x (wn 0..3), warp tile 32px x 64co
    const int wm = wid & 3, wn = wid >> 2;
    const u32 aoff = (u32)((wm*32 + (lane&15))*80 + (lane>>4)*16);
    const u32 boff = (u32)((wn*64 + (lane&7) + ((lane>>4)<<3))*80 + ((lane>>3)&1)*16);

    float acc[2][8][4];
    #pragma unroll
    for (int mf=0; mf<2; mf++)
        #pragma unroll
        for (int nf=0; nf<8; nf++)
            #pragma unroll
            for (int q=0; q<4; q++) acc[mf][nf][q] = 0.f;

    stage(0);
    stage(1);
    for (int it = 0; it < NITER; ++it) {
        if (it + 2 < NITER) stage(it + 2); else CP_COMMIT();
        CP_WAIT(2);
        __syncthreads();

        const u32 sA = sm0 + (u32)(it % NSTG) * STG;
        const u32 sB = sA + 20480;

        #pragma unroll
        for (int s = 0; s < 2; s++) {
            u32 a0[2][4], a1[2][4];
            #pragma unroll
            for (int mf = 0; mf < 2; mf++) {
                ldm_x4(a0[mf], sA + mf*1280 + s*32 + aoff);
                ldm_x4(a1[mf], sA + 10240 + mf*1280 + s*32 + aoff);
            }
            #pragma unroll
            for (int nfp = 0; nfp < 4; nfp++) {
                u32 rh[4], rl[4];
                ldm_x4(rh, sB + nfp*1280 + s*32 + boff);
                ldm_x4(rl, sB + 20480 + nfp*1280 + s*32 + boff);
                u32 bh0[2] = {rh[0], rh[1]}, bh1[2] = {rh[2], rh[3]};
                u32 bl0[2] = {rl[0], rl[1]}, bl1[2] = {rl[2], rl[3]};
                #pragma unroll
                for (int mf = 0; mf < 2; mf++) {
                    mma_bf16(acc[mf][nfp*2],   a0[mf], bh0);
                    mma_bf16(acc[mf][nfp*2+1], a0[mf], bh1);
                }
                #pragma unroll
                for (int mf = 0; mf < 2; mf++) {
                    mma_bf16(acc[mf][nfp*2],   a1[mf], bh0);
                    mma_bf16(acc[mf][nfp*2+1], a1[mf], bh1);
                }
                #pragma unroll
                for (int mf = 0; mf < 2; mf++) {
                    mma_bf16(acc[mf][nfp*2],   a0[mf], bl0);
                    mma_bf16(acc[mf][nfp*2+1], a0[mf], bl1);
                }
            }
        }
        __syncthreads();
    }

    // epilogue: warp covers 32px x 64co
    #pragma unroll
    for (int mf = 0; mf < 2; mf++) {
        #pragma unroll
        for (int nf = 0; nf < 8; nf++) {
            const int co = wn*64 + nf*8 + 2*(lane&3);
            const float bv0 = s_bias[co], bv1 = s_bias[co + 1];
            #pragma unroll
            for (int h2 = 0; h2 < 2; h2++) {
                const int m = m0 + wm*32 + mf*16 + (lane>>2) + h2*8;
                float v0 = fmaxf(acc[mf][nf][h2*2+0] + bv0, 0.f);
                float v1 = fmaxf(acc[mf][nf][h2*2+1] + bv1, 0.f);
                if (NHWC_OUT) {
                    bf16 h0_,l0_,h1_,l1_;
                    bf16_split(v0,h0_,l0_); bf16_split(v1,h1_,l1_);
                    size_t off = (bofs + m)*512 + inp*256 + co;
                    *(u32*)(outh+off) = pack_bf16(h0_,h1_);
                    *(u32*)(outl+off) = pack_bf16(l0_,l1_);
                } else {
                    outf[((size_t)(b*256 + co))*4096 + m]     = v0;
                    outf[((size_t)(b*256 + co + 1))*4096 + m] = v1;
                }
            }
        }
    }
}

// ===================== 1x1 conv (256->81) + relu + softmax =====================
__global__ void __launch_bounds__(256) conv1x1_softmax_kernel(
    const float* __restrict__ x2, const float* __restrict__ w3,
    const float* __restrict__ b3, float* __restrict__ kout)
{
    __shared__ float s_w[81*64];
    __shared__ float s_logit[81*64];
    __shared__ float s_m[64], s_r[64];
    const int tid = threadIdx.x, px = tid & 63, grp = tid >> 6;
    const int h = blockIdx.x, b = blockIdx.y;

    float acc[21];
    #pragma unroll
    for (int k = 0; k < 21; k++) { int co = grp + 4*k; acc[k] = (co < 81) ? b3[co] : 0.f; }
    const float* xb = x2 + ((size_t)b*256)*4096 + h*64 + px;

    for (int ci0 = 0; ci0 < 256; ci0 += 64) {
        __syncthreads();
        for (int j = tid; j < 81*64; j += 256) s_w[j] = w3[(j>>6)*256 + ci0 + (j&63)];
        __syncthreads();
        for (int i = 0; i < 64; i++) {
            float xv = __ldg(xb + (size_t)(ci0 + i)*4096);
            #pragma unroll
            for (int k = 0; k < 21; k++) { int co = grp + 4*k; if (co < 81) acc[k] += xv * s_w[co*64 + i]; }
        }
    }
    #pragma unroll
    for (int k = 0; k < 21; k++) { int co = grp + 4*k; if (co < 81) s_logit[co*64 + px] = fmaxf(acc[k], 0.f); }
    __syncthreads();
    if (tid < 64) {
        float m = -1e30f;
        for (int co = 0; co < 81; co++) m = fmaxf(m, s_logit[co*64 + tid]);
        float s = 0.f;
        for (int co = 0; co < 81; co++) s += __expf(s_logit[co*64 + tid] - m);
        s_m[tid] = m; s_r[tid] = 1.f / s;
    }
    __syncthreads();
    float m = s_m[px], rr = s_r[px];
    #pragma unroll
    for (int k = 0; k < 21; k++) {
        int co = grp + 4*k;
        if (co < 81)
            kout[((size_t)(b*81 + co)*4096) + h*64 + px] = __expf(s_logit[co*64 + px] - m) * rr;
    }
}

// ===================== spatially-variant 9x9 conv =====================
__global__ void __launch_bounds__(256) svc_kernel(
    const float* __restrict__ feats, const float* __restrict__ kern, float* __restrict__ out)
{
    __shared__ float k_s[81*64];
    __shared__ float f_s[16*16*24];
    const int tid = threadIdx.x;
    const int px_x = tid & 7, py = (tid>>3) & 7, cq = tid >> 6;
    const int px = py*8 + px_x;
    const int w0 = blockIdx.x*8, h0 = blockIdx.y*8;
    const int b = blockIdx.z >> 6, cbase = (blockIdx.z & 63) * 16;

    for (int j = tid; j < 81*64; j += 256) {
        int idx = j>>6, p = j&63;
        k_s[j] = kern[((size_t)(b*81 + idx)*64 + h0 + (p>>3))*64 + w0 + (p&7)];
    }
    for (int j = tid; j < 16*16*16; j += 256) {
        int c = j>>8, rw = (j>>4)&15, cl = j&15;
        int gr = h0 + rw - 4, gc = w0 + cl - 4;
        float v = 0.f;
        if ((unsigned)gr < 64u && (unsigned)gc < 64u)
            v = feats[((size_t)(b*1024 + cbase + c))*4096 + gr*64 + gc];
        f_s[c*384 + rw*24 + cl] = v;
    }
    __syncthreads();

    float acc[4] = {0.f,0.f,0.f,0.f};
    #pragma unroll 1
    for (int i = 0; i < 9; i++) {
        const int fb = (py+i)*24 + px_x + (cq*4)*384;
        #pragma unroll
        for (int j = 0; j < 9; j++) {
            float kv = k_s[(i*9 + j)*64 + px];
            #pragma unroll
            for (int c = 0; c < 4; c++) acc[c] += f_s[fb + j + c*384] * kv;
        }
    }
    size_t ob = ((size_t)(b*1024 + cbase + cq*4))*4096 + (size_t)(h0+py)*64 + w0 + px_x;
    #pragma unroll
    for (int c = 0; c < 4; c++) out[ob + (size_t)c*4096] = acc[c];
}

// ===================== launch =====================
extern "C" void kernel_launch(void* const* d_in, const int* in_sizes, int n_in,
                              void* d_out, int out_size)
{
    (void)in_sizes; (void)n_in; (void)out_size;
    const float* cur  = (const float*)d_in[0];
    const float* keyl = (const float*)d_in[1];
    const float* high = (const float*)d_in[2];
    const float* w1   = (const float*)d_in[3];
    const float* b1   = (const float*)d_in[4];
    const float* w2   = (const float*)d_in[5];
    const float* b2   = (const float*)d_in[6];
    const float* w3   = (const float*)d_in[7];
    const float* b3   = (const float*)d_in[8];
    float* out = (float*)d_out;

    bf16 *x0h,*x0l,*x1h,*x1l,*w1h,*w1l,*w2h,*w2l,*b1h,*b1l;
    float *buf2,*kern;
    cudaGetSymbolAddress((void**)&x0h, g_x0h);
    cudaGetSymbolAddress((void**)&x0l, g_x0l);
    cudaGetSymbolAddress((void**)&x1h, g_x1h);
    cudaGetSymbolAddress((void**)&x1l, g_x1l);
    cudaGetSymbolAddress((void**)&w1h, g_w1h);
    cudaGetSymbolAddress((void**)&w1l, g_w1l);
    cudaGetSymbolAddress((void**)&w2h, g_w2h);
    cudaGetSymbolAddress((void**)&w2l, g_w2l);
    cudaGetSymbolAddress((void**)&b1h, g_b1h);
    cudaGetSymbolAddress((void**)&b1l, g_b1l);
    cudaGetSymbolAddress((void**)&buf2, g_buf2);
    cudaGetSymbolAddress((void**)&kern, g_kern);

    const int DSM = NSTG*STG;
    cudaFuncSetAttribute(conv3x3_mma<1024,true,true>,  cudaFuncAttributeMaxDynamicSharedMemorySize, DSM);
    cudaFuncSetAttribute(conv3x3_mma<512,false,false>, cudaFuncAttributeMaxDynamicSharedMemorySize, DSM);

    transpose_split<<<dim3(64,16,4), 256>>>(cur,  x0h, x0l);
    transpose_split<<<dim3(64,16,4), 256>>>(keyl, x1h, x1l);
    prep_w<<<(9*32*8192+255)/256, 256>>>(w1, w1h, w1l, 1024, 32, 9*32*8192);
    prep_w<<<(9*16*8192+255)/256, 256>>>(w2, w2h, w2l, 512, 16, 9*16*8192);

    conv3x3_mma<1024,true,true><<<dim3(32,8), 512, DSM>>>(
        x0h, x0l, x1h, x1l, w1h, w1l, b1, b1h, b1l, nullptr);
    conv3x3_mma<512,false,false><<<dim3(32,4), 512, DSM>>>(
        b1h, b1l, nullptr, nullptr, w2h, w2l, b2, nullptr, nullptr, buf2);

    conv1x1_softmax_kernel<<<dim3(64,4), 256>>>(buf2, w3, b3, kern);
    svc_kernel<<<dim3(8,8,256), 256>>>(high, kern, out);
}

// round 7
// speedup vs baseline: 3.2242x; 1.6134x over previous
#include <cuda_runtime.h>
#include <cuda_bf16.h>
#include <cstdint>

typedef unsigned u32; typedef unsigned long long u64;
typedef __nv_bfloat16 bf16;

// ===================== PTX helpers (portable: sm_80-class only) =====================
__device__ __forceinline__ u32 smem_u32(const void* p){
    u32 a; asm("{ .reg .u64 t; cvta.to.shared.u64 t, %1; cvt.u32.u64 %0, t; }":"=r"(a):"l"(p)); return a;
}
#define CP_ASYNC_CA(dst, src, sz) \
    asm volatile("cp.async.ca.shared.global [%0], [%1], 16, %2;" :: "r"(dst), "l"(src), "r"(sz))
#define CP_ASYNC_CG(dst, src) \
    asm volatile("cp.async.cg.shared.global [%0], [%1], 16;" :: "r"(dst), "l"(src))
#define CP_COMMIT() asm volatile("cp.async.commit_group;" ::: "memory")
#define CP_WAIT(N)  asm volatile("cp.async.wait_group %0;" :: "n"(N) : "memory")

__device__ __forceinline__ void ldm_x4(u32* r, u32 addr){
    asm volatile("ldmatrix.sync.aligned.m8n8.x4.shared.b16 {%0,%1,%2,%3}, [%4];"
        : "=r"(r[0]),"=r"(r[1]),"=r"(r[2]),"=r"(r[3]) : "r"(addr));
}
__device__ __forceinline__ void mma_bf16(float* c, const u32* a, const u32* b){
    asm volatile("mma.sync.aligned.m16n8k16.row.col.f32.bf16.bf16.f32 "
        "{%0,%1,%2,%3}, {%4,%5,%6,%7}, {%8,%9}, {%0,%1,%2,%3};"
        : "+f"(c[0]),"+f"(c[1]),"+f"(c[2]),"+f"(c[3])
        : "r"(a[0]),"r"(a[1]),"r"(a[2]),"r"(a[3]), "r"(b[0]),"r"(b[1]));
}
__device__ __forceinline__ void bf16_split(float v, bf16& h, bf16& l){
    h = __float2bfloat16(v);
    l = __float2bfloat16(v - __bfloat162float(h));
}
__device__ __forceinline__ u32 pack_bf16(bf16 a, bf16 b){
    return (u32)__bfloat16_as_ushort(a) | ((u32)__bfloat16_as_ushort(b) << 16);
}
__device__ __forceinline__ float4 f4add(float4 a, float4 b){
    return make_float4(a.x+b.x, a.y+b.y, a.z+b.z, a.w+b.w);
}
__device__ __forceinline__ float4 f4sub(float4 a, float4 b){
    return make_float4(a.x-b.x, a.y-b.y, a.z-b.z, a.w-b.w);
}

// ===================== device scratch =====================
__device__ float g_xT[2ULL*4*4096*1024];        // NHWC fp32: [inp][b][px][ci]
__device__ bf16  g_V1h[2ULL*16*4096*1024];      // conv1 data transform hi
__device__ bf16  g_V1l[2ULL*16*4096*1024];      // conv1 data transform lo
__device__ bf16  g_U1h[16*32*256*32];           // conv1 weight transform [p][c][co][ci32]
__device__ bf16  g_U1l[16*32*256*32];
__device__ float g_M1[2ULL*16*4096*256];        // conv1 GEMM out (transform domain)
__device__ float g_buf1[4ULL*4096*512];         // NHWC fp32 concat(cur,key) conv1 out
__device__ bf16  g_V2h[16ULL*4096*512];
__device__ bf16  g_V2l[16ULL*4096*512];
__device__ bf16  g_U2h[16*16*256*32];
__device__ bf16  g_U2l[16*16*256*32];
__device__ float g_M2[16ULL*4096*256];
__device__ float g_buf2[4ULL*256*4096];         // NCHW conv2 out
__device__ float g_kern[4ULL*81*4096];          // NCHW softmax kernels

// ===================== NCHW -> NHWC fp32 (C=1024) =====================
__global__ void __launch_bounds__(256) nchw_to_nhwc(const float* __restrict__ x, float* __restrict__ xT){
    __shared__ float s[64*65];
    const int tid = threadIdx.x, px0 = blockIdx.x*64, ci0 = blockIdx.y*64, b = blockIdx.z;
    for (int j = tid; j < 4096; j += 256){
        int ci = j>>6, p = j&63;
        s[ci*65+p] = x[((size_t)(b*1024 + ci0+ci))*4096 + px0 + p];
    }
    __syncthreads();
    for (int j = tid; j < 4096; j += 256){
        int p = j>>6, ci = j&63;
        xT[((size_t)b*4096 + px0+p)*1024 + ci0 + ci] = s[ci*65+p];
    }
}

// ===================== Winograd weight transform: U = G g G^T, split bf16 ==========
// layout: [p 16][chunk c][co 256][ci%32], one thread per (co, ci)
__global__ void prep_wino_w(const float* __restrict__ w, bf16* __restrict__ uh, bf16* __restrict__ ul,
                            int CIN, int CH, int total)
{
    int idx = blockIdx.x*256 + threadIdx.x;
    if (idx >= total) return;
    int ci = idx % CIN, co = idx / CIN;
    const float* g = w + ((size_t)co*CIN + ci)*9;
    float g0[3] = {g[0], g[1], g[2]}, g1[3] = {g[3], g[4], g[5]}, g2[3] = {g[6], g[7], g[8]};
    float q[4][3];
    #pragma unroll
    for (int c = 0; c < 3; c++){
        q[0][c] = g0[c];
        q[1][c] = 0.5f*(g0[c] + g1[c] + g2[c]);
        q[2][c] = 0.5f*(g0[c] - g1[c] + g2[c]);
        q[3][c] = g2[c];
    }
    const int c = ci >> 5, cil = ci & 31;
    #pragma unroll
    for (int r = 0; r < 4; r++){
        float u[4];
        u[0] = q[r][0];
        u[1] = 0.5f*(q[r][0] + q[r][1] + q[r][2]);
        u[2] = 0.5f*(q[r][0] - q[r][1] + q[r][2]);
        u[3] = q[r][2];
        #pragma unroll
        for (int cc = 0; cc < 4; cc++){
            int p = r*4 + cc;
            bf16 h, l; bf16_split(u[cc], h, l);
            size_t o = ((size_t)((p*CH + c)*256 + co))*32 + cil;
            uh[o] = h; ul[o] = l;
        }
    }
}

// ===================== Winograd input transform: V = B^T d B, split bf16 ==========
// grid.x = 4096 tiles (b = gm>>10), block = CIN/4 threads, 4 ci per thread.
template<int CIN>
__global__ void wino_in(const float* __restrict__ x, bf16* __restrict__ vh, bf16* __restrict__ vl)
{
    const int gm = blockIdx.x;
    const int ci = threadIdx.x*4;
    const int b = gm>>10, t = gm&1023, ty = t>>5, tx = t&31;
    const float* src = x + ((size_t)b*4096)*CIN + ci;
    const float4 zero = make_float4(0.f,0.f,0.f,0.f);

    float4 z[4][4];
    #pragma unroll
    for (int c = 0; c < 4; c++){
        const int px = 2*tx - 1 + c;
        const bool okc = (unsigned)px < 64u;
        const int py0 = 2*ty - 1;
        float4 d0 = (okc && (unsigned)py0 < 64u)
                  ? *(const float4*)(src + (size_t)(py0*64 + px)*CIN) : zero;
        float4 d1 = okc ? *(const float4*)(src + (size_t)((py0+1)*64 + px)*CIN) : zero;
        float4 d2 = okc ? *(const float4*)(src + (size_t)((py0+2)*64 + px)*CIN) : zero;
        float4 d3 = (okc && (unsigned)(py0+3) < 64u)
                  ? *(const float4*)(src + (size_t)((py0+3)*64 + px)*CIN) : zero;
        z[0][c] = f4sub(d0, d2);
        z[1][c] = f4add(d1, d2);
        z[2][c] = f4sub(d2, d1);
        z[3][c] = f4sub(d1, d3);
    }
    #pragma unroll
    for (int r = 0; r < 4; r++){
        float4 vv[4];
        vv[0] = f4sub(z[r][0], z[r][2]);
        vv[1] = f4add(z[r][1], z[r][2]);
        vv[2] = f4sub(z[r][2], z[r][1]);
        vv[3] = f4sub(z[r][1], z[r][3]);
        #pragma unroll
        for (int c = 0; c < 4; c++){
            const int p = r*4 + c;
            const size_t o = ((size_t)(p*4096 + gm))*CIN + ci;
            bf16 h0,l0,h1,l1,h2,l2,h3,l3;
            bf16_split(vv[c].x, h0, l0); bf16_split(vv[c].y, h1, l1);
            bf16_split(vv[c].z, h2, l2); bf16_split(vv[c].w, h3, l3);
            *(uint2*)(vh + o) = make_uint2(pack_bf16(h0,h1), pack_bf16(h2,h3));
            *(uint2*)(vl + o) = make_uint2(pack_bf16(l0,l1), pack_bf16(l2,l3));
        }
    }
}

// ===================== Winograd-domain GEMM (mma.sync bf16, 3-product split) ======
// M=4096 (128/CTA), N=256, K=CIN per position. grid: (32, n_inp, 16 positions).
// 16 warps = 4(M) x 4(N), warp 32x64. Stage = 61440 B; 3-stage cp.async pipeline.
constexpr int STG = 61440;
constexpr int NSTG = 3;

template <int CIN>
__global__ void __launch_bounds__(512, 1) wino_gemm(
    const bf16* __restrict__ vh, const bf16* __restrict__ vl,
    const bf16* __restrict__ uh, const bf16* __restrict__ ul,
    float* __restrict__ mout)
{
    constexpr int CH = CIN/32;
    constexpr int NITER = CH;
    extern __shared__ char dsm[];

    const int tid = threadIdx.x, wid = tid>>5, lane = tid&31;
    const int m0 = blockIdx.x*128;
    const int p = blockIdx.z;
    const size_t voff = ((size_t)blockIdx.y*16 + p) * 4096 * CIN;
    const size_t moff = ((size_t)blockIdx.y*16 + p) * 4096 * 256;

    const u32 sm0 = smem_u32(dsm);

    // staging roles (identical structure to proven direct-conv kernel)
    const int au = tid >> 1;
    const int arow = au >> 1, ahalf = au & 1;
    const int asub = (tid & 1) * 32;                  // bytes within 64B row
    const int brow = tid >> 1, bhalf = tid & 1;

    auto stage = [&](int it){
        const int c = it;
        const u32 base = sm0 + (u32)(it % NSTG) * STG;
        // A: V row (m0+arow), 32B per thread
        {
            const bf16* src = (ahalf ? vl : vh) + voff
                + (size_t)(m0 + arow)*CIN + c*32 + (asub>>1);
            u32 dst = base + ahalf*10240 + arow*80 + asub;
            CP_ASYNC_CG(dst,      src);
            CP_ASYNC_CG(dst + 16, src + 8);
        }
        // B: U row brow (co), 64B
        {
            const bf16* src = (bhalf ? ul : uh)
                + ((size_t)((p*CH + c)*256 + brow)) * 32;
            u32 dst = base + 20480 + bhalf*20480 + brow*80;
            #pragma unroll
            for (int g = 0; g < 4; g++) CP_ASYNC_CG(dst + g*16, src + g*8);
        }
        CP_COMMIT();
    };

    const int wm = wid & 3, wn = wid >> 2;
    const u32 aoff = (u32)((wm*32 + (lane&15))*80 + (lane>>4)*16);
    const u32 boff = (u32)((wn*64 + (lane&7) + ((lane>>4)<<3))*80 + ((lane>>3)&1)*16);

    float acc[2][8][4];
    #pragma unroll
    for (int mf=0; mf<2; mf++)
        #pragma unroll
        for (int nf=0; nf<8; nf++)
            #pragma unroll
            for (int q=0; q<4; q++) acc[mf][nf][q] = 0.f;

    stage(0);
    stage(1);
    for (int it = 0; it < NITER; ++it) {
        if (it + 2 < NITER) stage(it + 2); else CP_COMMIT();
        CP_WAIT(2);
        __syncthreads();

        const u32 sA = sm0 + (u32)(it % NSTG) * STG;
        const u32 sB = sA + 20480;

        #pragma unroll
        for (int s = 0; s < 2; s++) {
            u32 a0[2][4], a1[2][4];
            #pragma unroll
            for (int mf = 0; mf < 2; mf++) {
                ldm_x4(a0[mf], sA + mf*1280 + s*32 + aoff);
                ldm_x4(a1[mf], sA + 10240 + mf*1280 + s*32 + aoff);
            }
            #pragma unroll
            for (int nfp = 0; nfp < 4; nfp++) {
                u32 rh[4], rl[4];
                ldm_x4(rh, sB + nfp*1280 + s*32 + boff);
                ldm_x4(rl, sB + 20480 + nfp*1280 + s*32 + boff);
                u32 bh0[2] = {rh[0], rh[1]}, bh1[2] = {rh[2], rh[3]};
                u32 bl0[2] = {rl[0], rl[1]}, bl1[2] = {rl[2], rl[3]};
                #pragma unroll
                for (int mf = 0; mf < 2; mf++) {
                    mma_bf16(acc[mf][nfp*2],   a0[mf], bh0);
                    mma_bf16(acc[mf][nfp*2+1], a0[mf], bh1);
                }
                #pragma unroll
                for (int mf = 0; mf < 2; mf++) {
                    mma_bf16(acc[mf][nfp*2],   a1[mf], bh0);
                    mma_bf16(acc[mf][nfp*2+1], a1[mf], bh1);
                }
                #pragma unroll
                for (int mf = 0; mf < 2; mf++) {
                    mma_bf16(acc[mf][nfp*2],   a0[mf], bl0);
                    mma_bf16(acc[mf][nfp*2+1], a0[mf], bl1);
                }
            }
        }
        __syncthreads();
    }

    // epilogue: raw fp32 transform-domain output (bias/relu applied post-transform)
    float* base = mout + moff;
    #pragma unroll
    for (int mf = 0; mf < 2; mf++) {
        #pragma unroll
        for (int nf = 0; nf < 8; nf++) {
            const int co = wn*64 + nf*8 + 2*(lane&3);
            #pragma unroll
            for (int h2 = 0; h2 < 2; h2++) {
                const int m = m0 + wm*32 + mf*16 + (lane>>2) + h2*8;
                float2 v = make_float2(acc[mf][nf][h2*2+0], acc[mf][nf][h2*2+1]);
                *(float2*)(base + (size_t)m*256 + co) = v;
            }
        }
    }
}

// ===================== Winograd output transform: Y = A^T M A + bias, relu ==========
// conv1 variant: writes NHWC fp32 buf1 with concat offset.
__global__ void __launch_bounds__(256) wino_out1(
    const float* __restrict__ min, const float* __restrict__ bias, float* __restrict__ out)
{
    const int inp = blockIdx.y;
    const int gm = blockIdx.x*4 + (threadIdx.x>>6);
    const int co = (threadIdx.x&63)*4;
    const float* base = min + ((size_t)inp*16)*4096*256 + (size_t)gm*256 + co;

    float4 m[16];
    #pragma unroll
    for (int p = 0; p < 16; p++) m[p] = *(const float4*)(base + (size_t)p*4096*256);

    float4 z0[4], z1[4];
    #pragma unroll
    for (int c = 0; c < 4; c++){
        z0[c] = f4add(f4add(m[c], m[4+c]), m[8+c]);
        z1[c] = f4sub(f4sub(m[4+c], m[8+c]), m[12+c]);
    }
    float4 y[2][2];
    y[0][0] = f4add(f4add(z0[0], z0[1]), z0[2]);
    y[0][1] = f4sub(f4sub(z0[1], z0[2]), z0[3]);
    y[1][0] = f4add(f4add(z1[0], z1[1]), z1[2]);
    y[1][1] = f4sub(f4sub(z1[1], z1[2]), z1[3]);

    const float4 bv = *(const float4*)(bias + co);
    const int b = gm>>10, t = gm&1023, ty = t>>5, tx = t&31;
    #pragma unroll
    for (int dr = 0; dr < 2; dr++)
        #pragma unroll
        for (int dc = 0; dc < 2; dc++){
            float4 v = f4add(y[dr][dc], bv);
            v.x = fmaxf(v.x, 0.f); v.y = fmaxf(v.y, 0.f);
            v.z = fmaxf(v.z, 0.f); v.w = fmaxf(v.w, 0.f);
            size_t o = ((size_t)(b*4096 + (2*ty+dr)*64 + 2*tx+dc))*512 + inp*256 + co;
            *(float4*)(out + o) = v;
        }
}

// conv2 variant: writes NCHW fp32 buf2.
__global__ void __launch_bounds__(256) wino_out2(
    const float* __restrict__ min, const float* __restrict__ bias, float* __restrict__ out)
{
    const int gm = blockIdx.x*4 + (threadIdx.x>>6);
    const int co = (threadIdx.x&63)*4;
    const float* base = min + (size_t)gm*256 + co;

    float4 m[16];
    #pragma unroll
    for (int p = 0; p < 16; p++) m[p] = *(const float4*)(base + (size_t)p*4096*256);

    float4 z0[4], z1[4];
    #pragma unroll
    for (int c = 0; c < 4; c++){
        z0[c] = f4add(f4add(m[c], m[4+c]), m[8+c]);
        z1[c] = f4sub(f4sub(m[4+c], m[8+c]), m[12+c]);
    }
    float4 y[2][2];
    y[0][0] = f4add(f4add(z0[0], z0[1]), z0[2]);
    y[0][1] = f4sub(f4sub(z0[1], z0[2]), z0[3]);
    y[1][0] = f4add(f4add(z1[0], z1[1]), z1[2]);
    y[1][1] = f4sub(f4sub(z1[1], z1[2]), z1[3]);

    const float4 bv = *(const float4*)(bias + co);
    const int b = gm>>10, t = gm&1023, ty = t>>5, tx = t&31;
    #pragma unroll
    for (int dr = 0; dr < 2; dr++)
        #pragma unroll
        for (int dc = 0; dc < 2; dc++){
            float4 v = f4add(y[dr][dc], bv);
            const int px = (2*ty+dr)*64 + 2*tx+dc;
            out[((size_t)(b*256 + co + 0))*4096 + px] = fmaxf(v.x, 0.f);
            out[((size_t)(b*256 + co + 1))*4096 + px] = fmaxf(v.y, 0.f);
            out[((size_t)(b*256 + co + 2))*4096 + px] = fmaxf(v.z, 0.f);
            out[((size_t)(b*256 + co + 3))*4096 + px] = fmaxf(v.w, 0.f);
        }
}

// ===================== 1x1 conv (256->81) + relu + softmax =====================
__global__ void __launch_bounds__(256) conv1x1_softmax_kernel(
    const float* __restrict__ x2, const float* __restrict__ w3,
    const float* __restrict__ b3, float* __restrict__ kout)
{
    __shared__ float s_w[81*64];
    __shared__ float s_logit[81*64];
    __shared__ float s_m[64], s_r[64];
    const int tid = threadIdx.x, px = tid & 63, grp = tid >> 6;
    const int h = blockIdx.x, b = blockIdx.y;

    float acc[21];
    #pragma unroll
    for (int k = 0; k < 21; k++) { int co = grp + 4*k; acc[k] = (co < 81) ? b3[co] : 0.f; }
    const float* xb = x2 + ((size_t)b*256)*4096 + h*64 + px;

    for (int ci0 = 0; ci0 < 256; ci0 += 64) {
        __syncthreads();
        for (int j = tid; j < 81*64; j += 256) s_w[j] = w3[(j>>6)*256 + ci0 + (j&63)];
        __syncthreads();
        for (int i = 0; i < 64; i++) {
            float xv = __ldg(xb + (size_t)(ci0 + i)*4096);
            #pragma unroll
            for (int k = 0; k < 21; k++) { int co = grp + 4*k; if (co < 81) acc[k] += xv * s_w[co*64 + i]; }
        }
    }
    #pragma unroll
    for (int k = 0; k < 21; k++) { int co = grp + 4*k; if (co < 81) s_logit[co*64 + px] = fmaxf(acc[k], 0.f); }
    __syncthreads();
    if (tid < 64) {
        float m = -1e30f;
        for (int co = 0; co < 81; co++) m = fmaxf(m, s_logit[co*64 + tid]);
        float s = 0.f;
        for (int co = 0; co < 81; co++) s += __expf(s_logit[co*64 + tid] - m);
        s_m[tid] = m; s_r[tid] = 1.f / s;
    }
    __syncthreads();
    float m = s_m[px], rr = s_r[px];
    #pragma unroll
    for (int k = 0; k < 21; k++) {
        int co = grp + 4*k;
        if (co < 81)
            kout[((size_t)(b*81 + co)*4096) + h*64 + px] = __expf(s_logit[co*64 + px] - m) * rr;
    }
}

// ===================== spatially-variant 9x9 conv =====================
__global__ void __launch_bounds__(256) svc_kernel(
    const float* __restrict__ feats, const float* __restrict__ kern, float* __restrict__ out)
{
    __shared__ float k_s[81*64];
    __shared__ float f_s[16*16*24];
    const int tid = threadIdx.x;
    const int px_x = tid & 7, py = (tid>>3) & 7, cq = tid >> 6;
    const int px = py*8 + px_x;
    const int w0 = blockIdx.x*8, h0 = blockIdx.y*8;
    const int b = blockIdx.z >> 6, cbase = (blockIdx.z & 63) * 16;

    for (int j = tid; j < 81*64; j += 256) {
        int idx = j>>6, p = j&63;
        k_s[j] = kern[((size_t)(b*81 + idx)*64 + h0 + (p>>3))*64 + w0 + (p&7)];
    }
    for (int j = tid; j < 16*16*16; j += 256) {
        int c = j>>8, rw = (j>>4)&15, cl = j&15;
        int gr = h0 + rw - 4, gc = w0 + cl - 4;
        float v = 0.f;
        if ((unsigned)gr < 64u && (unsigned)gc < 64u)
            v = feats[((size_t)(b*1024 + cbase + c))*4096 + gr*64 + gc];
        f_s[c*384 + rw*24 + cl] = v;
    }
    __syncthreads();

    float acc[4] = {0.f,0.f,0.f,0.f};
    #pragma unroll 1
    for (int i = 0; i < 9; i++) {
        const int fb = (py+i)*24 + px_x + (cq*4)*384;
        #pragma unroll
        for (int j = 0; j < 9; j++) {
            float kv = k_s[(i*9 + j)*64 + px];
            #pragma unroll
            for (int c = 0; c < 4; c++) acc[c] += f_s[fb + j + c*384] * kv;
        }
    }
    size_t ob = ((size_t)(b*1024 + cbase + cq*4))*4096 + (size_t)(h0+py)*64 + w0 + px_x;
    #pragma unroll
    for (int c = 0; c < 4; c++) out[ob + (size_t)c*4096] = acc[c];
}

// ===================== launch =====================
extern "C" void kernel_launch(void* const* d_in, const int* in_sizes, int n_in,
                              void* d_out, int out_size)
{
    (void)in_sizes; (void)n_in; (void)out_size;
    const float* cur  = (const float*)d_in[0];
    const float* keyl = (const float*)d_in[1];
    const float* high = (const float*)d_in[2];
    const float* w1   = (const float*)d_in[3];
    const float* b1   = (const float*)d_in[4];
    const float* w2   = (const float*)d_in[5];
    const float* b2   = (const float*)d_in[6];
    const float* w3   = (const float*)d_in[7];
    const float* b3   = (const float*)d_in[8];
    float* out = (float*)d_out;

    float *xT, *M1, *buf1, *M2, *buf2, *kern;
    bf16 *V1h,*V1l,*U1h,*U1l,*V2h,*V2l,*U2h,*U2l;
    cudaGetSymbolAddress((void**)&xT,  g_xT);
    cudaGetSymbolAddress((void**)&V1h, g_V1h);
    cudaGetSymbolAddress((void**)&V1l, g_V1l);
    cudaGetSymbolAddress((void**)&U1h, g_U1h);
    cudaGetSymbolAddress((void**)&U1l, g_U1l);
    cudaGetSymbolAddress((void**)&M1,  g_M1);
    cudaGetSymbolAddress((void**)&buf1, g_buf1);
    cudaGetSymbolAddress((void**)&V2h, g_V2h);
    cudaGetSymbolAddress((void**)&V2l, g_V2l);
    cudaGetSymbolAddress((void**)&U2h, g_U2h);
    cudaGetSymbolAddress((void**)&U2l, g_U2l);
    cudaGetSymbolAddress((void**)&M2,  g_M2);
    cudaGetSymbolAddress((void**)&buf2, g_buf2);
    cudaGetSymbolAddress((void**)&kern, g_kern);

    const int DSM = NSTG*STG;
    cudaFuncSetAttribute(wino_gemm<1024>, cudaFuncAttributeMaxDynamicSharedMemorySize, DSM);
    cudaFuncSetAttribute(wino_gemm<512>,  cudaFuncAttributeMaxDynamicSharedMemorySize, DSM);

    const size_t XSTRIDE = 4ULL*4096*1024;      // fp32 elems per input
    const size_t VSTRIDE = 16ULL*4096*1024;     // bf16 elems per input (conv1)

    // transposes + weight transforms
    nchw_to_nhwc<<<dim3(64,16,4), 256>>>(cur,  xT);
    nchw_to_nhwc<<<dim3(64,16,4), 256>>>(keyl, xT + XSTRIDE);
    prep_wino_w<<<(256*1024+255)/256, 256>>>(w1, U1h, U1l, 1024, 32, 256*1024);
    prep_wino_w<<<(256*512+255)/256, 256>>>(w2, U2h, U2l, 512, 16, 256*512);

    // conv1: input transform -> 16-pos GEMM -> output transform (+bias+relu, NHWC concat)
    wino_in<1024><<<4096, 256>>>(xT,           V1h,           V1l);
    wino_in<1024><<<4096, 256>>>(xT + XSTRIDE, V1h + VSTRIDE, V1l + VSTRIDE);
    wino_gemm<1024><<<dim3(32,2,16), 512, DSM>>>(V1h, V1l, U1h, U1l, M1);
    wino_out1<<<dim3(1024,2), 256>>>(M1, b1, buf1);

    // conv2: same pipeline on concat features (CIN=512), NCHW out
    wino_in<512><<<4096, 128>>>(buf1, V2h, V2l);
    wino_gemm<512><<<dim3(32,1,16), 512, DSM>>>(V2h, V2l, U2h, U2l, M2);
    wino_out2<<<1024, 256>>>(M2, b2, buf2);

    conv1x1_softmax_kernel<<<dim3(64,4), 256>>>(buf2, w3, b3, kern);
    svc_kernel<<<dim3(8,8,256), 256>>>(high, kern, out);
}

// round 8
// speedup vs baseline: 4.4127x; 1.3686x over previous
#include <cuda_runtime.h>
#include <cuda_bf16.h>
#include <cstdint>

typedef unsigned u32; typedef unsigned long long u64;
typedef __nv_bfloat16 bf16;

// ===================== PTX helpers (portable: sm_80-class only) =====================
__device__ __forceinline__ u32 smem_u32(const void* p){
    u32 a; asm("{ .reg .u64 t; cvta.to.shared.u64 t, %1; cvt.u32.u64 %0, t; }":"=r"(a):"l"(p)); return a;
}
#define CP_ASYNC_CG(dst, src) \
    asm volatile("cp.async.cg.shared.global [%0], [%1], 16;" :: "r"(dst), "l"(src))
#define CP_COMMIT() asm volatile("cp.async.commit_group;" ::: "memory")
#define CP_WAIT(N)  asm volatile("cp.async.wait_group %0;" :: "n"(N) : "memory")

__device__ __forceinline__ void ldm_x4(u32* r, u32 addr){
    asm volatile("ldmatrix.sync.aligned.m8n8.x4.shared.b16 {%0,%1,%2,%3}, [%4];"
        : "=r"(r[0]),"=r"(r[1]),"=r"(r[2]),"=r"(r[3]) : "r"(addr));
}
__device__ __forceinline__ void mma_bf16(float* c, const u32* a, const u32* b){
    asm volatile("mma.sync.aligned.m16n8k16.row.col.f32.bf16.bf16.f32 "
        "{%0,%1,%2,%3}, {%4,%5,%6,%7}, {%8,%9}, {%0,%1,%2,%3};"
        : "+f"(c[0]),"+f"(c[1]),"+f"(c[2]),"+f"(c[3])
        : "r"(a[0]),"r"(a[1]),"r"(a[2]),"r"(a[3]), "r"(b[0]),"r"(b[1]));
}
__device__ __forceinline__ void bf16_split(float v, bf16& h, bf16& l){
    h = __float2bfloat16(v);
    l = __float2bfloat16(v - __bfloat162float(h));
}
__device__ __forceinline__ u32 pack_bf16(bf16 a, bf16 b){
    return (u32)__bfloat16_as_ushort(a) | ((u32)__bfloat16_as_ushort(b) << 16);
}

// float2 arithmetic
__device__ __forceinline__ float2 operator+(float2 a, float2 b){ return make_float2(a.x+b.x, a.y+b.y); }
__device__ __forceinline__ float2 operator-(float2 a, float2 b){ return make_float2(a.x-b.x, a.y-b.y); }
__device__ __forceinline__ float2 operator*(float s, float2 a){ return make_float2(s*a.x, s*a.y); }

// ===================== device scratch =====================
__device__ float g_xT[2ULL*4*4096*1024];        // NHWC fp32: [inp][b][px][ci]
__device__ bf16  g_V1h[2ULL*36*1024*1024];      // [inp][p36][gm1024][ci1024]
__device__ bf16  g_V1l[2ULL*36*1024*1024];
__device__ bf16  g_U1h[36*32*256*32];           // [p][chunk][co][ci32]
__device__ bf16  g_U1l[36*32*256*32];
__device__ float g_M1[2ULL*36*1024*256];        // [inp][p][gm][co]
__device__ float g_buf1[4ULL*4096*512];         // NHWC fp32 concat(cur,key)
__device__ bf16  g_V2h[36ULL*1024*512];
__device__ bf16  g_V2l[36ULL*1024*512];
__device__ bf16  g_U2h[36*16*256*32];
__device__ bf16  g_U2l[36*16*256*32];
__device__ float g_M2[36ULL*1024*256];
__device__ float g_buf2[4ULL*256*4096];         // NCHW conv2 out
__device__ float g_kern[4ULL*81*4096];          // NCHW softmax kernels

// ===================== NCHW -> NHWC fp32 (C=1024) =====================
__global__ void __launch_bounds__(256) nchw_to_nhwc(const float* __restrict__ x, float* __restrict__ xT){
    __shared__ float s[64*65];
    const int tid = threadIdx.x, px0 = blockIdx.x*64, ci0 = blockIdx.y*64, b = blockIdx.z;
    for (int j = tid; j < 4096; j += 256){
        int ci = j>>6, p = j&63;
        s[ci*65+p] = x[((size_t)(b*1024 + ci0+ci))*4096 + px0 + p];
    }
    __syncthreads();
    for (int j = tid; j < 4096; j += 256){
        int p = j>>6, ci = j&63;
        xT[((size_t)b*4096 + px0+p)*1024 + ci0 + ci] = s[ci*65+p];
    }
}

// ===================== F(4,3) weight transform: U = G g G^T (36 pos), bf16 split ====
__global__ void prep_wino_w4(const float* __restrict__ w, bf16* __restrict__ uh, bf16* __restrict__ ul,
                             int CIN, int CH, int total)
{
    int idx = blockIdx.x*256 + threadIdx.x;
    if (idx >= total) return;
    int ci = idx % CIN, co = idx / CIN;
    const float* g = w + ((size_t)co*CIN + ci)*9;
    float q[6][3];
    #pragma unroll
    for (int c = 0; c < 3; c++){
        float g0 = g[c], g1 = g[3+c], g2 = g[6+c];
        q[0][c] = 0.25f*g0;
        q[1][c] = -(g0 + g1 + g2) * (1.f/6.f);
        q[2][c] = (-g0 + g1 - g2) * (1.f/6.f);
        q[3][c] = g0*(1.f/24.f) + g1*(1.f/12.f) + g2*(1.f/6.f);
        q[4][c] = g0*(1.f/24.f) - g1*(1.f/12.f) + g2*(1.f/6.f);
        q[5][c] = g2;
    }
    const int c = ci >> 5, cil = ci & 31;
    #pragma unroll
    for (int r = 0; r < 6; r++){
        float a = q[r][0], b2 = q[r][1], c2 = q[r][2];
        float u[6];
        u[0] = 0.25f*a;
        u[1] = -(a + b2 + c2) * (1.f/6.f);
        u[2] = (-a + b2 - c2) * (1.f/6.f);
        u[3] = a*(1.f/24.f) + b2*(1.f/12.f) + c2*(1.f/6.f);
        u[4] = a*(1.f/24.f) - b2*(1.f/12.f) + c2*(1.f/6.f);
        u[5] = c2;
        #pragma unroll
        for (int cc = 0; cc < 6; cc++){
            int p = r*6 + cc;
            bf16 h, l; bf16_split(u[cc], h, l);
            size_t o = ((size_t)((p*CH + c)*256 + co))*32 + cil;
            uh[o] = h; ul[o] = l;
        }
    }
}

// ===================== F(4,3) input transform: V = B^T d B, bf16 split ==============
// grid (1024 tiles, n_inp); block = CIN/2 threads, 2 ci per thread.
template<int CIN>
__global__ void __launch_bounds__(512) wino_in4(
    const float* __restrict__ x, bf16* __restrict__ vh, bf16* __restrict__ vl,
    size_t xstride, size_t vstride)
{
    const int gm = blockIdx.x;
    const int inp = blockIdx.y;
    const int ci = threadIdx.x*2;
    const int b = gm>>8, t = gm&255, ty = t>>4, tx = t&15;
    const float* src = x + inp*xstride + ((size_t)b*4096)*CIN + ci;
    bf16* voh = vh + inp*vstride;
    bf16* vol = vl + inp*vstride;
    const float2 zero = make_float2(0.f, 0.f);

    float2 z[6][6];
    const int py0 = 4*ty - 1;
    #pragma unroll
    for (int c = 0; c < 6; c++){
        const int px = 4*tx - 1 + c;
        const bool okc = (unsigned)px < 64u;
        float2 d[6];
        #pragma unroll
        for (int j = 0; j < 6; j++){
            const int py = py0 + j;
            d[j] = (okc && (unsigned)py < 64u)
                 ? *(const float2*)(src + (size_t)(py*64 + px)*CIN) : zero;
        }
        z[0][c] = 4.f*d[0] - 5.f*d[2] + d[4];
        z[1][c] = -4.f*d[1] - 4.f*d[2] + d[3] + d[4];
        z[2][c] =  4.f*d[1] - 4.f*d[2] - d[3] + d[4];
        z[3][c] = -2.f*d[1] - d[2] + 2.f*d[3] + d[4];
        z[4][c] =  2.f*d[1] - d[2] - 2.f*d[3] + d[4];
        z[5][c] =  4.f*d[1] - 5.f*d[3] + d[5];
    }
    #pragma unroll
    for (int r = 0; r < 6; r++){
        float2 v[6];
        v[0] = 4.f*z[r][0] - 5.f*z[r][2] + z[r][4];
        v[1] = -4.f*z[r][1] - 4.f*z[r][2] + z[r][3] + z[r][4];
        v[2] =  4.f*z[r][1] - 4.f*z[r][2] - z[r][3] + z[r][4];
        v[3] = -2.f*z[r][1] - z[r][2] + 2.f*z[r][3] + z[r][4];
        v[4] =  2.f*z[r][1] - z[r][2] - 2.f*z[r][3] + z[r][4];
        v[5] =  4.f*z[r][1] - 5.f*z[r][3] + z[r][5];
        #pragma unroll
        for (int c = 0; c < 6; c++){
            const int p = r*6 + c;
            const size_t o = ((size_t)p*1024 + gm)*CIN + ci;
            bf16 h0,l0,h1,l1;
            bf16_split(v[c].x, h0, l0); bf16_split(v[c].y, h1, l1);
            *(u32*)(voh + o) = pack_bf16(h0, h1);
            *(u32*)(vol + o) = pack_bf16(l0, l1);
        }
    }
}

// ===================== Winograd-domain GEMM (mma.sync bf16, 3-product split) ======
// Per position p: M=1024/input (128/CTA), N=256, K=CIN. grid: (8, n_inp, 36).
// 16 warps = 4(M) x 4(N), warp 32x64. Stage = 61440 B; 3-stage cp.async pipeline.
constexpr int STG = 61440;
constexpr int NSTG = 3;

template <int CIN>
__global__ void __launch_bounds__(512, 1) wino_gemm(
    const bf16* __restrict__ vh, const bf16* __restrict__ vl,
    const bf16* __restrict__ uh, const bf16* __restrict__ ul,
    float* __restrict__ mout)
{
    constexpr int CH = CIN/32;
    constexpr int NITER = CH;
    extern __shared__ char dsm[];

    const int tid = threadIdx.x, wid = tid>>5, lane = tid&31;
    const int m0 = blockIdx.x*128;
    const int p = blockIdx.z;
    const size_t voff = ((size_t)blockIdx.y*36 + p) * 1024 * CIN;
    const size_t moff = ((size_t)blockIdx.y*36 + p) * 1024 * 256;

    const u32 sm0 = smem_u32(dsm);

    const int au = tid >> 1;
    const int arow = au >> 1, ahalf = au & 1;
    const int asub = (tid & 1) * 32;
    const int brow = tid >> 1, bhalf = tid & 1;

    auto stage = [&](int it){
        const int c = it;
        const u32 base = sm0 + (u32)(it % NSTG) * STG;
        {
            const bf16* src = (ahalf ? vl : vh) + voff
                + (size_t)(m0 + arow)*CIN + c*32 + (asub>>1);
            u32 dst = base + ahalf*10240 + arow*80 + asub;
            CP_ASYNC_CG(dst,      src);
            CP_ASYNC_CG(dst + 16, src + 8);
        }
        {
            const bf16* src = (bhalf ? ul : uh)
                + ((size_t)((p*CH + c)*256 + brow)) * 32;
            u32 dst = base + 20480 + bhalf*20480 + brow*80;
            #pragma unroll
            for (int g = 0; g < 4; g++) CP_ASYNC_CG(dst + g*16, src + g*8);
        }
        CP_COMMIT();
    };

    const int wm = wid & 3, wn = wid >> 2;
    const u32 aoff = (u32)((wm*32 + (lane&15))*80 + (lane>>4)*16);
    const u32 boff = (u32)((wn*64 + (lane&7) + ((lane>>4)<<3))*80 + ((lane>>3)&1)*16);

    float acc[2][8][4];
    #pragma unroll
    for (int mf=0; mf<2; mf++)
        #pragma unroll
        for (int nf=0; nf<8; nf++)
            #pragma unroll
            for (int q=0; q<4; q++) acc[mf][nf][q] = 0.f;

    stage(0);
    stage(1);
    for (int it = 0; it < NITER; ++it) {
        if (it + 2 < NITER) stage(it + 2); else CP_COMMIT();
        CP_WAIT(2);
        __syncthreads();

        const u32 sA = sm0 + (u32)(it % NSTG) * STG;
        const u32 sB = sA + 20480;

        #pragma unroll
        for (int s = 0; s < 2; s++) {
            u32 a0[2][4], a1[2][4];
            #pragma unroll
            for (int mf = 0; mf < 2; mf++) {
                ldm_x4(a0[mf], sA + mf*1280 + s*32 + aoff);
                ldm_x4(a1[mf], sA + 10240 + mf*1280 + s*32 + aoff);
            }
            #pragma unroll
            for (int nfp = 0; nfp < 4; nfp++) {
                u32 rh[4], rl[4];
                ldm_x4(rh, sB + nfp*1280 + s*32 + boff);
                ldm_x4(rl, sB + 20480 + nfp*1280 + s*32 + boff);
                u32 bh0[2] = {rh[0], rh[1]}, bh1[2] = {rh[2], rh[3]};
                u32 bl0[2] = {rl[0], rl[1]}, bl1[2] = {rl[2], rl[3]};
                #pragma unroll
                for (int mf = 0; mf < 2; mf++) {
                    mma_bf16(acc[mf][nfp*2],   a0[mf], bh0);
                    mma_bf16(acc[mf][nfp*2+1], a0[mf], bh1);
                }
                #pragma unroll
                for (int mf = 0; mf < 2; mf++) {
                    mma_bf16(acc[mf][nfp*2],   a1[mf], bh0);
                    mma_bf16(acc[mf][nfp*2+1], a1[mf], bh1);
                }
                #pragma unroll
                for (int mf = 0; mf < 2; mf++) {
                    mma_bf16(acc[mf][nfp*2],   a0[mf], bl0);
                    mma_bf16(acc[mf][nfp*2+1], a0[mf], bl1);
                }
            }
        }
        __syncthreads();
    }

    float* base = mout + moff;
    #pragma unroll
    for (int mf = 0; mf < 2; mf++) {
        #pragma unroll
        for (int nf = 0; nf < 8; nf++) {
            const int co = wn*64 + nf*8 + 2*(lane&3);
            #pragma unroll
            for (int h2 = 0; h2 < 2; h2++) {
                const int m = m0 + wm*32 + mf*16 + (lane>>2) + h2*8;
                float2 v = make_float2(acc[mf][nf][h2*2+0], acc[mf][nf][h2*2+1]);
                *(float2*)(base + (size_t)m*256 + co) = v;
            }
        }
    }
}

// ===================== F(4,3) output transform: Y = A^T M A + bias, relu ============
// block = 128 threads (2 co each); grid (1024 gm, n_inp).
__global__ void __launch_bounds__(128) wino_out4_nhwc(
    const float* __restrict__ min, const float* __restrict__ bias, float* __restrict__ out)
{
    const int inp = blockIdx.y;
    const int gm = blockIdx.x;
    const int co = threadIdx.x*2;
    const float* base = min + ((size_t)inp*36)*1024*256 + (size_t)gm*256 + co;

    float2 m[36];
    #pragma unroll
    for (int p = 0; p < 36; p++) m[p] = *(const float2*)(base + (size_t)p*1024*256);

    float2 tt[4][6];
    #pragma unroll
    for (int c = 0; c < 6; c++){
        float2 m0=m[c], m1=m[6+c], m2=m[12+c], m3=m[18+c], m4=m[24+c], m5=m[30+c];
        tt[0][c] = m0 + m1 + m2 + m3 + m4;
        tt[1][c] = m1 - m2 + 2.f*m3 - 2.f*m4;
        tt[2][c] = m1 + m2 + 4.f*m3 + 4.f*m4;
        tt[3][c] = m1 - m2 + 8.f*m3 - 8.f*m4 + m5;
    }
    const float2 bv = *(const float2*)(bias + co);
    const int b = gm>>8, t = gm&255, ty = t>>4, tx = t&15;
    #pragma unroll
    for (int r = 0; r < 4; r++){
        float2 y[4];
        y[0] = tt[r][0] + tt[r][1] + tt[r][2] + tt[r][3] + tt[r][4];
        y[1] = tt[r][1] - tt[r][2] + 2.f*tt[r][3] - 2.f*tt[r][4];
        y[2] = tt[r][1] + tt[r][2] + 4.f*tt[r][3] + 4.f*tt[r][4];
        y[3] = tt[r][1] - tt[r][2] + 8.f*tt[r][3] - 8.f*tt[r][4] + tt[r][5];
        #pragma unroll
        for (int c = 0; c < 4; c++){
            float2 v = y[c] + bv;
            v.x = fmaxf(v.x, 0.f); v.y = fmaxf(v.y, 0.f);
            const int px = (4*ty + r)*64 + 4*tx + c;
            *(float2*)(out + ((size_t)(b*4096 + px))*512 + inp*256 + co) = v;
        }
    }
}

__global__ void __launch_bounds__(128) wino_out4_nchw(
    const float* __restrict__ min, const float* __restrict__ bias, float* __restrict__ out)
{
    const int gm = blockIdx.x;
    const int co = threadIdx.x*2;
    const float* base = min + (size_t)gm*256 + co;

    float2 m[36];
    #pragma unroll
    for (int p = 0; p < 36; p++) m[p] = *(const float2*)(base + (size_t)p*1024*256);

    float2 tt[4][6];
    #pragma unroll
    for (int c = 0; c < 6; c++){
        float2 m0=m[c], m1=m[6+c], m2=m[12+c], m3=m[18+c], m4=m[24+c], m5=m[30+c];
        tt[0][c] = m0 + m1 + m2 + m3 + m4;
        tt[1][c] = m1 - m2 + 2.f*m3 - 2.f*m4;
        tt[2][c] = m1 + m2 + 4.f*m3 + 4.f*m4;
        tt[3][c] = m1 - m2 + 8.f*m3 - 8.f*m4 + m5;
    }
    const float2 bv = *(const float2*)(bias + co);
    const int b = gm>>8, t = gm&255, ty = t>>4, tx = t&15;
    #pragma unroll
    for (int r = 0; r < 4; r++){
        float2 y[4];
        y[0] = tt[r][0] + tt[r][1] + tt[r][2] + tt[r][3] + tt[r][4];
        y[1] = tt[r][1] - tt[r][2] + 2.f*tt[r][3] - 2.f*tt[r][4];
        y[2] = tt[r][1] + tt[r][2] + 4.f*tt[r][3] + 4.f*tt[r][4];
        y[3] = tt[r][1] - tt[r][2] + 8.f*tt[r][3] - 8.f*tt[r][4] + tt[r][5];
        #pragma unroll
        for (int c = 0; c < 4; c++){
            float2 v = y[c] + bv;
            const int px = (4*ty + r)*64 + 4*tx + c;
            out[((size_t)(b*256 + co + 0))*4096 + px] = fmaxf(v.x, 0.f);
            out[((size_t)(b*256 + co + 1))*4096 + px] = fmaxf(v.y, 0.f);
        }
    }
}

// ===================== 1x1 conv (256->81) + relu + softmax =====================
__global__ void __launch_bounds__(256) conv1x1_softmax_kernel(
    const float* __restrict__ x2, const float* __restrict__ w3,
    const float* __restrict__ b3, float* __restrict__ kout)
{
    __shared__ float s_w[81*64];
    __shared__ float s_logit[81*64];
    __shared__ float s_m[64], s_r[64];
    const int tid = threadIdx.x, px = tid & 63, grp = tid >> 6;
    const int h = blockIdx.x, b = blockIdx.y;

    float acc[21];
    #pragma unroll
    for (int k = 0; k < 21; k++) { int co = grp + 4*k; acc[k] = (co < 81) ? b3[co] : 0.f; }
    const float* xb = x2 + ((size_t)b*256)*4096 + h*64 + px;

    for (int ci0 = 0; ci0 < 256; ci0 += 64) {
        __syncthreads();
        for (int j = tid; j < 81*64; j += 256) s_w[j] = w3[(j>>6)*256 + ci0 + (j&63)];
        __syncthreads();
        for (int i = 0; i < 64; i++) {
            float xv = __ldg(xb + (size_t)(ci0 + i)*4096);
            #pragma unroll
            for (int k = 0; k < 21; k++) { int co = grp + 4*k; if (co < 81) acc[k] += xv * s_w[co*64 + i]; }
        }
    }
    #pragma unroll
    for (int k = 0; k < 21; k++) { int co = grp + 4*k; if (co < 81) s_logit[co*64 + px] = fmaxf(acc[k], 0.f); }
    __syncthreads();
    if (tid < 64) {
        float m = -1e30f;
        for (int co = 0; co < 81; co++) m = fmaxf(m, s_logit[co*64 + tid]);
        float s = 0.f;
        for (int co = 0; co < 81; co++) s += __expf(s_logit[co*64 + tid] - m);
        s_m[tid] = m; s_r[tid] = 1.f / s;
    }
    __syncthreads();
    float m = s_m[px], rr = s_r[px];
    #pragma unroll
    for (int k = 0; k < 21; k++) {
        int co = grp + 4*k;
        if (co < 81)
            kout[((size_t)(b*81 + co)*4096) + h*64 + px] = __expf(s_logit[co*64 + px] - m) * rr;
    }
}

// ===================== spatially-variant 9x9 conv =====================
__global__ void __launch_bounds__(256) svc_kernel(
    const float* __restrict__ feats, const float* __restrict__ kern, float* __restrict__ out)
{
    __shared__ float k_s[81*64];
    __shared__ float f_s[16*16*24];
    const int tid = threadIdx.x;
    const int px_x = tid & 7, py = (tid>>3) & 7, cq = tid >> 6;
    const int px = py*8 + px_x;
    const int w0 = blockIdx.x*8, h0 = blockIdx.y*8;
    const int b = blockIdx.z >> 6, cbase = (blockIdx.z & 63) * 16;

    for (int j = tid; j < 81*64; j += 256) {
        int idx = j>>6, p = j&63;
        k_s[j] = kern[((size_t)(b*81 + idx)*64 + h0 + (p>>3))*64 + w0 + (p&7)];
    }
    for (int j = tid; j < 16*16*16; j += 256) {
        int c = j>>8, rw = (j>>4)&15, cl = j&15;
        int gr = h0 + rw - 4, gc = w0 + cl - 4;
        float v = 0.f;
        if ((unsigned)gr < 64u && (unsigned)gc < 64u)
            v = feats[((size_t)(b*1024 + cbase + c))*4096 + gr*64 + gc];
        f_s[c*384 + rw*24 + cl] = v;
    }
    __syncthreads();

    float acc[4] = {0.f,0.f,0.f,0.f};
    #pragma unroll 1
    for (int i = 0; i < 9; i++) {
        const int fb = (py+i)*24 + px_x + (cq*4)*384;
        #pragma unroll
        for (int j = 0; j < 9; j++) {
            float kv = k_s[(i*9 + j)*64 + px];
            #pragma unroll
            for (int c = 0; c < 4; c++) acc[c] += f_s[fb + j + c*384] * kv;
        }
    }
    size_t ob = ((size_t)(b*1024 + cbase + cq*4))*4096 + (size_t)(h0+py)*64 + w0 + px_x;
    #pragma unroll
    for (int c = 0; c < 4; c++) out[ob + (size_t)c*4096] = acc[c];
}

// ===================== launch =====================
extern "C" void kernel_launch(void* const* d_in, const int* in_sizes, int n_in,
                              void* d_out, int out_size)
{
    (void)in_sizes; (void)n_in; (void)out_size;
    const float* cur  = (const float*)d_in[0];
    const float* keyl = (const float*)d_in[1];
    const float* high = (const float*)d_in[2];
    const float* w1   = (const float*)d_in[3];
    const float* b1   = (const float*)d_in[4];
    const float* w2   = (const float*)d_in[5];
    const float* b2   = (const float*)d_in[6];
    const float* w3   = (const float*)d_in[7];
    const float* b3   = (const float*)d_in[8];
    float* out = (float*)d_out;

    float *xT, *M1, *buf1, *M2, *buf2, *kern;
    bf16 *V1h,*V1l,*U1h,*U1l,*V2h,*V2l,*U2h,*U2l;
    cudaGetSymbolAddress((void**)&xT,  g_xT);
    cudaGetSymbolAddress((void**)&V1h, g_V1h);
    cudaGetSymbolAddress((void**)&V1l, g_V1l);
    cudaGetSymbolAddress((void**)&U1h, g_U1h);
    cudaGetSymbolAddress((void**)&U1l, g_U1l);
    cudaGetSymbolAddress((void**)&M1,  g_M1);
    cudaGetSymbolAddress((void**)&buf1, g_buf1);
    cudaGetSymbolAddress((void**)&V2h, g_V2h);
    cudaGetSymbolAddress((void**)&V2l, g_V2l);
    cudaGetSymbolAddress((void**)&U2h, g_U2h);
    cudaGetSymbolAddress((void**)&U2l, g_U2l);
    cudaGetSymbolAddress((void**)&M2,  g_M2);
    cudaGetSymbolAddress((void**)&buf2, g_buf2);
    cudaGetSymbolAddress((void**)&kern, g_kern);

    const int DSM = NSTG*STG;
    cudaFuncSetAttribute(wino_gemm<1024>, cudaFuncAttributeMaxDynamicSharedMemorySize, DSM);
    cudaFuncSetAttribute(wino_gemm<512>,  cudaFuncAttributeMaxDynamicSharedMemorySize, DSM);

    const size_t XSTRIDE = 4ULL*4096*1024;       // fp32 elems per input
    const size_t V1STRIDE = 36ULL*1024*1024;     // bf16 elems per input

    nchw_to_nhwc<<<dim3(64,16,4), 256>>>(cur,  xT);
    nchw_to_nhwc<<<dim3(64,16,4), 256>>>(keyl, xT + XSTRIDE);
    prep_wino_w4<<<(256*1024+255)/256, 256>>>(w1, U1h, U1l, 1024, 32, 256*1024);
    prep_wino_w4<<<(256*512+255)/256, 256>>>(w2, U2h, U2l, 512, 16, 256*512);

    // conv1
    wino_in4<1024><<<dim3(1024,2), 512>>>(xT, V1h, V1l, XSTRIDE, V1STRIDE);
    wino_gemm<1024><<<dim3(8,2,36), 512, DSM>>>(V1h, V1l, U1h, U1l, M1);
    wino_out4_nhwc<<<dim3(1024,2), 128>>>(M1, b1, buf1);

    // conv2
    wino_in4<512><<<dim3(1024,1), 256>>>(buf1, V2h, V2l, 0, 0);
    wino_gemm<512><<<dim3(8,1,36), 512, DSM>>>(V2h, V2l, U2h, U2l, M2);
    wino_out4_nchw<<<1024, 128>>>(M2, b2, buf2);

    conv1x1_softmax_kernel<<<dim3(64,4), 256>>>(buf2, w3, b3, kern);
    svc_kernel<<<dim3(8,8,256), 256>>>(high, kern, out);
}